// round 1
// baseline (speedup 1.0000x reference)
#include <cuda_runtime.h>
#include <cstddef>

#define Hdim  768
#define Fdim  512
#define Bdim  64
#define Mrows (Bdim * Fdim)       /* 32768 */
#define Vocab 256
#define NHEAD 12
#define DH    64

// ---------------- scratch (no allocations allowed) ----------------
__device__ float g_h1[(size_t)Mrows * Hdim];
__device__ float g_q [(size_t)Mrows * Hdim];
__device__ float g_o [(size_t)Mrows * Hdim];
__device__ float g_k [NHEAD * DH * Vocab];   // [head][d][v]
__device__ float g_v [NHEAD * Vocab * DH];   // [head][v][d]

// ---------------- A-tile loader (optionally fused GCN row mix) ----
template <int MIX>
__device__ __forceinline__ float4 ld_a(const float* __restrict__ A, int m, int K, int ka)
{
    const float* p = A + (size_t)m * K + ka;
    float4 v = *(const float4*)p;
    if (MIX) {
        int f = m & (Fdim - 1);
        if ((unsigned)(f - 1) < 4u) {           // f in {1,2,3,4}
            float s1 = (f == 1) ? 0.70710678118654752440f : 0.5f;
            float4 pv = *(const float4*)(p - K); // row f-1, same batch
            v.x = 0.5f * v.x + s1 * pv.x;
            v.y = 0.5f * v.y + s1 * pv.y;
            v.z = 0.5f * v.z + s1 * pv.z;
            v.w = 0.5f * v.w + s1 * pv.w;
        }
    }
    return v;
}

// ---------------- generic TN GEMM: C = A(MxK) * W(NxK)^T + bias ---
// 128x128 block tile, 16 k-slice, 256 threads, 8x8 micro-tile, dbl-buffered
template <int MIX>
__global__ void __launch_bounds__(256)
gemm_tn(const float* __restrict__ A, const float* __restrict__ W,
        const float* __restrict__ bias, float* __restrict__ C,
        int M, int N, int K)
{
    __shared__ float As[2][16][128];
    __shared__ float Bs[2][16][128];
    const int tid = threadIdx.x;
    const int m0  = blockIdx.y << 7;
    const int n0  = blockIdx.x << 7;
    const int lr  = tid >> 2;            // 0..63 loader row
    const int lc  = (tid & 3) << 2;      // k offset 0/4/8/12
    const int ty  = tid >> 4;            // 0..15 (m groups of 8)
    const int tx  = tid & 15;            // 0..15 (n groups of 8)
    const int nk  = K >> 4;

    float acc[8][8];
#pragma unroll
    for (int i = 0; i < 8; i++)
#pragma unroll
        for (int j = 0; j < 8; j++) acc[i][j] = 0.f;

    float4 rA0 = ld_a<MIX>(A, m0 + lr,      K, lc);
    float4 rA1 = ld_a<MIX>(A, m0 + lr + 64, K, lc);
    float4 rB0 = *(const float4*)(W + (size_t)(n0 + lr)      * K + lc);
    float4 rB1 = *(const float4*)(W + (size_t)(n0 + lr + 64) * K + lc);

    // store tile 0
    As[0][lc + 0][lr] = rA0.x; As[0][lc + 1][lr] = rA0.y;
    As[0][lc + 2][lr] = rA0.z; As[0][lc + 3][lr] = rA0.w;
    As[0][lc + 0][lr + 64] = rA1.x; As[0][lc + 1][lr + 64] = rA1.y;
    As[0][lc + 2][lr + 64] = rA1.z; As[0][lc + 3][lr + 64] = rA1.w;
    Bs[0][lc + 0][lr] = rB0.x; Bs[0][lc + 1][lr] = rB0.y;
    Bs[0][lc + 2][lr] = rB0.z; Bs[0][lc + 3][lr] = rB0.w;
    Bs[0][lc + 0][lr + 64] = rB1.x; Bs[0][lc + 1][lr + 64] = rB1.y;
    Bs[0][lc + 2][lr + 64] = rB1.z; Bs[0][lc + 3][lr + 64] = rB1.w;
    __syncthreads();

    for (int kt = 0; kt < nk; kt++) {
        const int cur = kt & 1;
        if (kt + 1 < nk) {
            const int ka = ((kt + 1) << 4) + lc;
            rA0 = ld_a<MIX>(A, m0 + lr,      K, ka);
            rA1 = ld_a<MIX>(A, m0 + lr + 64, K, ka);
            rB0 = *(const float4*)(W + (size_t)(n0 + lr)      * K + ka);
            rB1 = *(const float4*)(W + (size_t)(n0 + lr + 64) * K + ka);
        }
#pragma unroll
        for (int kk = 0; kk < 16; kk++) {
            float4 a0 = *(const float4*)&As[cur][kk][ty * 8];
            float4 a1 = *(const float4*)&As[cur][kk][ty * 8 + 4];
            float4 b0 = *(const float4*)&Bs[cur][kk][tx * 8];
            float4 b1 = *(const float4*)&Bs[cur][kk][tx * 8 + 4];
            float av[8] = {a0.x, a0.y, a0.z, a0.w, a1.x, a1.y, a1.z, a1.w};
            float bw[8] = {b0.x, b0.y, b0.z, b0.w, b1.x, b1.y, b1.z, b1.w};
#pragma unroll
            for (int i = 0; i < 8; i++)
#pragma unroll
                for (int j = 0; j < 8; j++)
                    acc[i][j] += av[i] * bw[j];
        }
        if (kt + 1 < nk) {
            const int nb = cur ^ 1;
            As[nb][lc + 0][lr] = rA0.x; As[nb][lc + 1][lr] = rA0.y;
            As[nb][lc + 2][lr] = rA0.z; As[nb][lc + 3][lr] = rA0.w;
            As[nb][lc + 0][lr + 64] = rA1.x; As[nb][lc + 1][lr + 64] = rA1.y;
            As[nb][lc + 2][lr + 64] = rA1.z; As[nb][lc + 3][lr + 64] = rA1.w;
            Bs[nb][lc + 0][lr] = rB0.x; Bs[nb][lc + 1][lr] = rB0.y;
            Bs[nb][lc + 2][lr] = rB0.z; Bs[nb][lc + 3][lr] = rB0.w;
            Bs[nb][lc + 0][lr + 64] = rB1.x; Bs[nb][lc + 1][lr + 64] = rB1.y;
            Bs[nb][lc + 2][lr + 64] = rB1.z; Bs[nb][lc + 3][lr + 64] = rB1.w;
        }
        __syncthreads();
    }

    float bv[8];
#pragma unroll
    for (int j = 0; j < 8; j++) bv[j] = bias[n0 + tx * 8 + j];
#pragma unroll
    for (int i = 0; i < 8; i++) {
        float* cp = C + (size_t)(m0 + ty * 8 + i) * N + n0 + tx * 8;
        float4 o0 = make_float4(acc[i][0] + bv[0], acc[i][1] + bv[1],
                                acc[i][2] + bv[2], acc[i][3] + bv[3]);
        float4 o1 = make_float4(acc[i][4] + bv[4], acc[i][5] + bv[5],
                                acc[i][6] + bv[6], acc[i][7] + bv[7]);
        *(float4*)cp = o0;
        *(float4*)(cp + 4) = o1;
    }
}

// ---------------- K/V projection (batch-independent, computed once) ----
// k[v,n] = sum_h WE[h,v] * Wk[n,h] + bk[n]   (same for v-proj)
__global__ void __launch_bounds__(256)
kv_kernel(const float* __restrict__ WE, const float* __restrict__ ipw,
          const float* __restrict__ ipb, float* __restrict__ gK,
          float* __restrict__ gV)
{
    const int n     = blockIdx.x;        // 0..767 output channel
    const int which = blockIdx.y;        // 0 -> K, 1 -> V
    const float* W  = ipw + (size_t)(which + 1) * Hdim * Hdim + (size_t)n * Hdim;
    const float  bb = ipb[(which + 1) * Hdim + n];
    const int vv    = threadIdx.x;       // 0..255 vocab position

    float acc = 0.f;
#pragma unroll 8
    for (int h = 0; h < Hdim; h++)
        acc += WE[h * Vocab + vv] * W[h];
    acc += bb;

    const int head = n >> 6, d = n & 63;
    if (which == 0) gK[head * (DH * Vocab) + d * Vocab + vv] = acc;   // [head][d][v]
    else            gV[head * (Vocab * DH) + vv * DH + d]   = acc;   // [head][v][d]
}

// ---------------- fused attention ----------------
// grid(8, 12, 64): 64 q-rows x full 256 keys per block. 256 threads.
#define ATTN_SMEM_FLOATS (64 * 256 + 256 * 64 + 256 * 64 + 64 * 64 + 64)
#define ATTN_SMEM_BYTES  (ATTN_SMEM_FLOATS * 4)

__global__ void __launch_bounds__(256)
attn_kernel(const float* __restrict__ Q, const float* __restrict__ Kt,
            const float* __restrict__ Vv, float* __restrict__ O)
{
    extern __shared__ float sm[];
    float* Ks   = sm;                     // [64][256]  (d-major)
    float* Vs   = Ks + 64 * 256;          // [256][64]  (key-major)
    float* S    = Vs + 256 * 64;          // [256][64]  scores transposed [key][m]
    float* Qs   = S  + 256 * 64;          // [64][64]   (d-major) transposed q
    float* rinv = Qs + 64 * 64;           // [64]

    const int tid = threadIdx.x;
    const int qb  = blockIdx.x << 6;
    const int hd  = blockIdx.y;
    const int b   = blockIdx.z;

    // load K, V tiles (contiguous, already pre-transposed in gmem)
    {
        const float4* ksrc = (const float4*)(Kt + (size_t)hd * DH * Vocab);
        const float4* vsrc = (const float4*)(Vv + (size_t)hd * Vocab * DH);
        float4* kdst = (float4*)Ks;
        float4* vdst = (float4*)Vs;
        for (int i = tid; i < 4096; i += 256) kdst[i] = ksrc[i];
        for (int i = tid; i < 4096; i += 256) vdst[i] = vsrc[i];
    }
    // load Q transposed: Qs[d][m]
#pragma unroll
    for (int r = 0; r < 4; r++) {
        int idx = tid + (r << 8);         // 0..1023
        int m   = idx >> 4;
        int d4  = (idx & 15) << 2;
        float4 v = *(const float4*)(Q + ((size_t)(b * Fdim + qb + m)) * Hdim + hd * DH + d4);
        Qs[(d4 + 0) * 64 + m] = v.x;
        Qs[(d4 + 1) * 64 + m] = v.y;
        Qs[(d4 + 2) * 64 + m] = v.z;
        Qs[(d4 + 3) * 64 + m] = v.w;
    }
    __syncthreads();

    // Phase 1: scores 64m x 256keys, K-dim = 64
    {
        const int ty = tid >> 5;          // 0..7  -> m = ty*8..
        const int tx = tid & 31;          // 0..31 -> key = tx*8..
        float acc[8][8];
#pragma unroll
        for (int i = 0; i < 8; i++)
#pragma unroll
            for (int j = 0; j < 8; j++) acc[i][j] = 0.f;

#pragma unroll 4
        for (int d = 0; d < 64; d++) {
            float4 a0 = *(const float4*)&Qs[d * 64 + ty * 8];
            float4 a1 = *(const float4*)&Qs[d * 64 + ty * 8 + 4];
            float4 b0 = *(const float4*)&Ks[d * 256 + tx * 8];
            float4 b1 = *(const float4*)&Ks[d * 256 + tx * 8 + 4];
            float av[8] = {a0.x, a0.y, a0.z, a0.w, a1.x, a1.y, a1.z, a1.w};
            float bw[8] = {b0.x, b0.y, b0.z, b0.w, b1.x, b1.y, b1.z, b1.w};
#pragma unroll
            for (int i = 0; i < 8; i++)
#pragma unroll
                for (int j = 0; j < 8; j++)
                    acc[i][j] += av[i] * bw[j];
        }
        // store transposed, scaled by dh^-0.5 = 0.125
#pragma unroll
        for (int j = 0; j < 8; j++) {
            float* sp = &S[(tx * 8 + j) * 64 + ty * 8];
            *(float4*)sp = make_float4(acc[0][j] * 0.125f, acc[1][j] * 0.125f,
                                       acc[2][j] * 0.125f, acc[3][j] * 0.125f);
            *(float4*)(sp + 4) = make_float4(acc[4][j] * 0.125f, acc[5][j] * 0.125f,
                                             acc[6][j] * 0.125f, acc[7][j] * 0.125f);
        }
    }
    __syncthreads();

    // Softmax over keys: 4 threads per row
    {
        const int row = tid >> 2;
        const int tr  = tid & 3;
        float mx = -1e30f;
        for (int k = tr * 64; k < tr * 64 + 64; k++)
            mx = fmaxf(mx, S[k * 64 + row]);
        mx = fmaxf(mx, __shfl_xor_sync(0xFFFFFFFFu, mx, 1));
        mx = fmaxf(mx, __shfl_xor_sync(0xFFFFFFFFu, mx, 2));
        float sum = 0.f;
        for (int k = tr * 64; k < tr * 64 + 64; k++) {
            float e = __expf(S[k * 64 + row] - mx);
            S[k * 64 + row] = e;
            sum += e;
        }
        sum += __shfl_xor_sync(0xFFFFFFFFu, sum, 1);
        sum += __shfl_xor_sync(0xFFFFFFFFu, sum, 2);
        if (tr == 0) rinv[row] = 1.0f / sum;
    }
    __syncthreads();

    // Phase 2: O = P(64x256) @ V(256x64)
    {
        const int ty2 = tid >> 4;         // m group of 4
        const int tx2 = tid & 15;         // d group of 4
        float oa[4][4];
#pragma unroll
        for (int i = 0; i < 4; i++)
#pragma unroll
            for (int j = 0; j < 4; j++) oa[i][j] = 0.f;

#pragma unroll 4
        for (int k = 0; k < 256; k++) {
            float4 a = *(const float4*)&S[k * 64 + ty2 * 4];
            float4 bb = *(const float4*)&Vs[k * 64 + tx2 * 4];
            float av[4] = {a.x, a.y, a.z, a.w};
            float bw[4] = {bb.x, bb.y, bb.z, bb.w};
#pragma unroll
            for (int i = 0; i < 4; i++)
#pragma unroll
                for (int j = 0; j < 4; j++)
                    oa[i][j] += av[i] * bw[j];
        }
#pragma unroll
        for (int i = 0; i < 4; i++) {
            int m = ty2 * 4 + i;
            float sc = rinv[m];
            float4 w = make_float4(oa[i][0] * sc, oa[i][1] * sc,
                                   oa[i][2] * sc, oa[i][3] * sc);
            *(float4*)(O + ((size_t)(b * Fdim + qb + m)) * Hdim + hd * DH + tx2 * 4) = w;
        }
    }
}

// ---------------- launch ----------------
extern "C" void kernel_launch(void* const* d_in, const int* in_sizes, int n_in,
                              void* d_out, int out_size)
{
    const float* x   = (const float*)d_in[0];
    const float* WE  = (const float*)d_in[1];
    const float* Wl  = (const float*)d_in[2];
    const float* bl  = (const float*)d_in[3];
    const float* Wg  = (const float*)d_in[4];
    const float* bg  = (const float*)d_in[5];
    const float* ipw = (const float*)d_in[6];
    const float* ipb = (const float*)d_in[7];
    const float* Wo  = (const float*)d_in[8];
    const float* bo  = (const float*)d_in[9];

    float* out    = (float*)d_out;
    float* x_time = out;                                   // first tuple element
    float* x_out  = out + (size_t)Mrows * Hdim;            // second tuple element

    float *h1, *q, *o, *gk, *gv;
    cudaGetSymbolAddress((void**)&h1, g_h1);
    cudaGetSymbolAddress((void**)&q,  g_q);
    cudaGetSymbolAddress((void**)&o,  g_o);
    cudaGetSymbolAddress((void**)&gk, g_k);
    cudaGetSymbolAddress((void**)&gv, g_v);

    dim3 blk(256);
    dim3 gg(Hdim / 128, Mrows / 128);   // (6, 256)

    // 1) h1 = x @ W_lin^T + b_lin
    gemm_tn<0><<<gg, blk>>>(x, Wl, bl, h1, Mrows, Hdim, 256);
    // 2) x_time = gcn_mix(h1) @ W_gcn^T + b_gcn   (mix fused into A loads)
    gemm_tn<1><<<gg, blk>>>(h1, Wg, bg, x_time, Mrows, Hdim, Hdim);
    // 3) q = x_time @ Wq^T + bq
    gemm_tn<0><<<gg, blk>>>(x_time, ipw, ipb, q, Mrows, Hdim, Hdim);
    // 4) k/v projections (batch-independent, once)
    kv_kernel<<<dim3(Hdim, 2), 256>>>(WE, ipw, ipb, gk, gv);
    // 5) fused attention
    cudaFuncSetAttribute(attn_kernel, cudaFuncAttributeMaxDynamicSharedMemorySize,
                         ATTN_SMEM_BYTES);
    attn_kernel<<<dim3(Fdim / 64, NHEAD, Bdim), 256, ATTN_SMEM_BYTES>>>(q, gk, gv, o);
    // 6) x_out = o @ out_proj_w^T + out_proj_b
    gemm_tn<0><<<gg, blk>>>(o, Wo, bo, x_out, Mrows, Hdim, Hdim);
}

// round 6
// speedup vs baseline: 1.4945x; 1.4945x over previous
#include <cuda_runtime.h>
#include <cuda_fp16.h>
#include <cstdint>
#include <cstddef>

#define Hdim  768
#define Fdim  512
#define Bdim  64
#define Mrows (Bdim * Fdim)       /* 32768 */
#define Vocab 256
#define NHEAD 12
#define DH    64

// ---------------- scratch (no allocations allowed) ----------------
__device__ float g_h1[(size_t)Mrows * Hdim];
__device__ float g_q [(size_t)Mrows * Hdim];
__device__ float g_o [(size_t)Mrows * Hdim];
__device__ float g_k [NHEAD * DH * Vocab];   // [head][d][v]
__device__ float g_v [NHEAD * Vocab * DH];   // [head][v][d]

__device__ __forceinline__ uint32_t smem_u32(const void* p) {
    uint32_t r;
    asm("{ .reg .u64 t; cvta.to.shared.u64 t, %1; cvt.u32.u64 %0, t; }"
        : "=r"(r) : "l"(p));
    return r;
}

__device__ __forceinline__ void ldm_x4(uint32_t& r0, uint32_t& r1,
                                       uint32_t& r2, uint32_t& r3, uint32_t addr) {
    asm volatile("ldmatrix.sync.aligned.m8n8.x4.shared.b16 {%0,%1,%2,%3}, [%4];"
                 : "=r"(r0), "=r"(r1), "=r"(r2), "=r"(r3) : "r"(addr));
}
__device__ __forceinline__ void mma16816(float* d, const uint32_t* a,
                                         uint32_t b0, uint32_t b1) {
    asm volatile(
        "mma.sync.aligned.m16n8k16.row.col.f32.f16.f16.f32 "
        "{%0,%1,%2,%3}, {%4,%5,%6,%7}, {%8,%9}, {%0,%1,%2,%3};"
        : "+f"(d[0]), "+f"(d[1]), "+f"(d[2]), "+f"(d[3])
        : "r"(a[0]), "r"(a[1]), "r"(a[2]), "r"(a[3]), "r"(b0), "r"(b1));
}

// ================= HMMA GEMM: C = A(MxK) * W(NxK)^T + bias =================
// 128x128 tile, BK=32, 256 thr, warp grid 2(m)x4(n), warp tile 64x32,
// fp16 hi/lo split (3 mma), smem [128][40] fp16 per tile (pad -> no conflicts)
#define GSTRIDE 40
#define TILE_H  (128 * GSTRIDE)              /* fp16 units per tile */
#define G_SMEM_BYTES (4 * TILE_H * 2)        /* Ahi Alo Bhi Blo = 40960 B */

template <int MIX>
__device__ __forceinline__ void stage_load(const float* __restrict__ src,
                                           int row0, int K, int kc, int tid,
                                           float4 st[4])
{
    const int row = tid >> 1;
    const int seg = (tid & 1) << 4;
    const float* p = src + (size_t)(row0 + row) * K + kc + seg;
    st[0] = *(const float4*)(p + 0);
    st[1] = *(const float4*)(p + 4);
    st[2] = *(const float4*)(p + 8);
    st[3] = *(const float4*)(p + 12);
    if (MIX) {
        int f = (row0 + row) & (Fdim - 1);
        if ((unsigned)(f - 1) < 4u) {        // f in {1,2,3,4}
            float s1 = (f == 1) ? 0.70710678118654752440f : 0.5f;
#pragma unroll
            for (int j = 0; j < 4; j++) {
                float4 pv = *(const float4*)(p - K + 4 * j);
                st[j].x = 0.5f * st[j].x + s1 * pv.x;
                st[j].y = 0.5f * st[j].y + s1 * pv.y;
                st[j].z = 0.5f * st[j].z + s1 * pv.z;
                st[j].w = 0.5f * st[j].w + s1 * pv.w;
            }
        }
    }
}

__device__ __forceinline__ void stage_store(const float4 st[4], __half* hi,
                                            __half* lo, int tid)
{
    const int row = tid >> 1;
    const int seg = (tid & 1) << 4;
    const float* f = (const float*)st;
    uint32_t hp[8], lp[8];
#pragma unroll
    for (int j = 0; j < 8; j++) {
        float a = f[2 * j], b = f[2 * j + 1];
        __half ha = __float2half_rn(a), hb = __float2half_rn(b);
        float la = a - __half2float(ha), lb = b - __half2float(hb);
        __half2 h2 = __halves2half2(ha, hb);
        __half2 l2 = __floats2half2_rn(la, lb);
        hp[j] = *(uint32_t*)&h2;
        lp[j] = *(uint32_t*)&l2;
    }
    uint32_t off = row * GSTRIDE + seg;       // fp16 units, 16B-aligned (80|row)
    *(uint4*)(hi + off)     = make_uint4(hp[0], hp[1], hp[2], hp[3]);
    *(uint4*)(hi + off + 8) = make_uint4(hp[4], hp[5], hp[6], hp[7]);
    *(uint4*)(lo + off)     = make_uint4(lp[0], lp[1], lp[2], lp[3]);
    *(uint4*)(lo + off + 8) = make_uint4(lp[4], lp[5], lp[6], lp[7]);
}

template <int MIX>
__global__ void __launch_bounds__(256)
gemm_mma(const float* __restrict__ A, const float* __restrict__ W,
         const float* __restrict__ bias, float* __restrict__ C, int K)
{
    extern __shared__ __align__(16) __half gsm[];
    __half* Ahi = gsm;
    __half* Alo = gsm + TILE_H;
    __half* Bhi = gsm + 2 * TILE_H;
    __half* Blo = gsm + 3 * TILE_H;

    const int tid = threadIdx.x;
    const int wid = tid >> 5;
    const int ln  = tid & 31;
    const int wm  = wid >> 2;                 // 0..1 -> 64 rows
    const int wn  = wid & 3;                  // 0..3 -> 32 cols
    const int m0  = blockIdx.y << 7;
    const int n0  = blockIdx.x << 7;

    // ldmatrix per-lane address pieces (fp16 units)
    const int lrow  = ln & 15;
    const int lcol8 = (ln >> 4) << 3;
    const uint32_t uAhi = smem_u32(Ahi), uAlo = smem_u32(Alo);
    const uint32_t uBhi = smem_u32(Bhi), uBlo = smem_u32(Blo);

    float acc[4][4][4];
#pragma unroll
    for (int i = 0; i < 4; i++)
#pragma unroll
        for (int j = 0; j < 4; j++)
#pragma unroll
            for (int r = 0; r < 4; r++) acc[i][j][r] = 0.f;

    const int nchunk = K >> 5;
    float4 sa[4], sb[4];

    stage_load<MIX>(A, m0, K, 0, tid, sa);
    stage_load<0>  (W, n0, K, 0, tid, sb);
    stage_store(sa, Ahi, Alo, tid);
    stage_store(sb, Bhi, Blo, tid);
    __syncthreads();

    for (int c = 0; c < nchunk; c++) {
        if (c + 1 < nchunk) {
            stage_load<MIX>(A, m0, K, (c + 1) << 5, tid, sa);
            stage_load<0>  (W, n0, K, (c + 1) << 5, tid, sb);
        }
#pragma unroll
        for (int ks = 0; ks < 2; ks++) {
            const uint32_t cadd = (ks * 16 + lcol8) * 2;  // bytes
            uint32_t ah[4][4], al[4][4], bh[2][4], bl[2][4];
#pragma unroll
            for (int tm = 0; tm < 4; tm++) {
                uint32_t off = ((wm * 64 + tm * 16 + lrow) * GSTRIDE) * 2 + cadd;
                ldm_x4(ah[tm][0], ah[tm][1], ah[tm][2], ah[tm][3], uAhi + off);
                ldm_x4(al[tm][0], al[tm][1], al[tm][2], al[tm][3], uAlo + off);
            }
#pragma unroll
            for (int pp = 0; pp < 2; pp++) {
                uint32_t off = ((wn * 32 + pp * 16 + lrow) * GSTRIDE) * 2 + cadd;
                ldm_x4(bh[pp][0], bh[pp][1], bh[pp][2], bh[pp][3], uBhi + off);
                ldm_x4(bl[pp][0], bl[pp][1], bl[pp][2], bl[pp][3], uBlo + off);
            }
#pragma unroll
            for (int tm = 0; tm < 4; tm++)
#pragma unroll
                for (int tn = 0; tn < 4; tn++) {
                    const int pp = tn >> 1, ii = tn & 1;
                    // reg order from x4 on B: {b0(t0), b0(t1), b1(t0), b1(t1)}
                    uint32_t b0h = bh[pp][ii], b1h = bh[pp][ii + 2];
                    uint32_t b0l = bl[pp][ii], b1l = bl[pp][ii + 2];
                    mma16816(acc[tm][tn], ah[tm], b0h, b1h);   // hi*hi
                    mma16816(acc[tm][tn], ah[tm], b0l, b1l);   // hi*lo
                    mma16816(acc[tm][tn], al[tm], b0h, b1h);   // lo*hi
                }
        }
        __syncthreads();
        if (c + 1 < nchunk) {
            stage_store(sa, Ahi, Alo, tid);
            stage_store(sb, Bhi, Blo, tid);
            __syncthreads();
        }
    }

    // epilogue: d-frag layout: rows g, g+8 (g = ln>>2), cols (ln&3)*2, +1
    const int g  = ln >> 2;
    const int c2 = (ln & 3) << 1;
#pragma unroll
    for (int tm = 0; tm < 4; tm++) {
#pragma unroll
        for (int tn = 0; tn < 4; tn++) {
            const int col = n0 + wn * 32 + tn * 8 + c2;
            const float b0 = bias[col], b1 = bias[col + 1];
            const int r0 = m0 + wm * 64 + tm * 16 + g;
            float2 v0 = make_float2(acc[tm][tn][0] + b0, acc[tm][tn][1] + b1);
            float2 v1 = make_float2(acc[tm][tn][2] + b0, acc[tm][tn][3] + b1);
            *(float2*)(C + (size_t)r0 * Hdim + col)       = v0;
            *(float2*)(C + (size_t)(r0 + 8) * Hdim + col) = v1;
        }
    }
}

// ---------------- K/V projection (batch-independent, once) ----------------
__global__ void __launch_bounds__(256)
kv_kernel(const float* __restrict__ WE, const float* __restrict__ ipw,
          const float* __restrict__ ipb, float* __restrict__ gK,
          float* __restrict__ gV)
{
    const int nb    = blockIdx.x << 2;
    const int which = blockIdx.y;          // 0 -> K, 1 -> V
    const float* W  = ipw + (size_t)(which + 1) * Hdim * Hdim;
    const int vv    = threadIdx.x;

    float a0 = 0.f, a1 = 0.f, a2 = 0.f, a3 = 0.f;
#pragma unroll 4
    for (int h = 0; h < Hdim; h++) {
        float we = WE[h * Vocab + vv];
        a0 += we * W[(size_t)(nb + 0) * Hdim + h];
        a1 += we * W[(size_t)(nb + 1) * Hdim + h];
        a2 += we * W[(size_t)(nb + 2) * Hdim + h];
        a3 += we * W[(size_t)(nb + 3) * Hdim + h];
    }
    float acc[4] = {a0, a1, a2, a3};
#pragma unroll
    for (int j = 0; j < 4; j++) {
        int n = nb + j;
        float r = acc[j] + ipb[(which + 1) * Hdim + n];
        int head = n >> 6, d = n & 63;
        if (which == 0) gK[head * (DH * Vocab) + d * Vocab + vv] = r;
        else            gV[head * (Vocab * DH) + vv * DH + d]   = r;
    }
}

// ---------------- fused attention (SIMT, R1-proven) ----------------
#define ATTN_SMEM_FLOATS (64 * 256 + 256 * 64 + 256 * 64 + 64 * 64 + 64)
#define ATTN_SMEM_BYTES  (ATTN_SMEM_FLOATS * 4)

__global__ void __launch_bounds__(256)
attn_kernel(const float* __restrict__ Q, const float* __restrict__ Kt,
            const float* __restrict__ Vv, float* __restrict__ O)
{
    extern __shared__ float sm[];
    float* Ks   = sm;                     // [64][256]
    float* Vs   = Ks + 64 * 256;          // [256][64]
    float* S    = Vs + 256 * 64;          // [256][64]  scores^T [key][m]
    float* Qs   = S  + 256 * 64;          // [64][64]   q^T [d][m]
    float* rinv = Qs + 64 * 64;           // [64]

    const int tid = threadIdx.x;
    const int qb  = blockIdx.x << 6;
    const int hd  = blockIdx.y;
    const int b   = blockIdx.z;

    {
        const float4* ksrc = (const float4*)(Kt + (size_t)hd * DH * Vocab);
        const float4* vsrc = (const float4*)(Vv + (size_t)hd * Vocab * DH);
        float4* kdst = (float4*)Ks;
        float4* vdst = (float4*)Vs;
        for (int i = tid; i < 4096; i += 256) kdst[i] = ksrc[i];
        for (int i = tid; i < 4096; i += 256) vdst[i] = vsrc[i];
    }
#pragma unroll
    for (int r = 0; r < 4; r++) {
        int idx = tid + (r << 8);
        int m   = idx >> 4;
        int d4  = (idx & 15) << 2;
        float4 v = *(const float4*)(Q + ((size_t)(b * Fdim + qb + m)) * Hdim + hd * DH + d4);
        Qs[(d4 + 0) * 64 + m] = v.x;
        Qs[(d4 + 1) * 64 + m] = v.y;
        Qs[(d4 + 2) * 64 + m] = v.z;
        Qs[(d4 + 3) * 64 + m] = v.w;
    }
    __syncthreads();

    {
        const int ty = tid >> 5;
        const int tx = tid & 31;
        float acc[8][8];
#pragma unroll
        for (int i = 0; i < 8; i++)
#pragma unroll
            for (int j = 0; j < 8; j++) acc[i][j] = 0.f;
#pragma unroll 4
        for (int d = 0; d < 64; d++) {
            float4 a0 = *(const float4*)&Qs[d * 64 + ty * 8];
            float4 a1 = *(const float4*)&Qs[d * 64 + ty * 8 + 4];
            float4 b0 = *(const float4*)&Ks[d * 256 + tx * 8];
            float4 b1 = *(const float4*)&Ks[d * 256 + tx * 8 + 4];
            float av[8] = {a0.x, a0.y, a0.z, a0.w, a1.x, a1.y, a1.z, a1.w};
            float bw[8] = {b0.x, b0.y, b0.z, b0.w, b1.x, b1.y, b1.z, b1.w};
#pragma unroll
            for (int i = 0; i < 8; i++)
#pragma unroll
                for (int j = 0; j < 8; j++)
                    acc[i][j] += av[i] * bw[j];
        }
#pragma unroll
        for (int j = 0; j < 8; j++) {
            float* sp = &S[(tx * 8 + j) * 64 + ty * 8];
            *(float4*)sp = make_float4(acc[0][j]*0.125f, acc[1][j]*0.125f,
                                       acc[2][j]*0.125f, acc[3][j]*0.125f);
            *(float4*)(sp + 4) = make_float4(acc[4][j]*0.125f, acc[5][j]*0.125f,
                                             acc[6][j]*0.125f, acc[7][j]*0.125f);
        }
    }
    __syncthreads();

    {
        const int row = tid >> 2;
        const int tr  = tid & 3;
        float mx = -1e30f;
        for (int k = tr * 64; k < tr * 64 + 64; k++)
            mx = fmaxf(mx, S[k * 64 + row]);
        mx = fmaxf(mx, __shfl_xor_sync(0xFFFFFFFFu, mx, 1));
        mx = fmaxf(mx, __shfl_xor_sync(0xFFFFFFFFu, mx, 2));
        float sum = 0.f;
        for (int k = tr * 64; k < tr * 64 + 64; k++) {
            float e = __expf(S[k * 64 + row] - mx);
            S[k * 64 + row] = e;
            sum += e;
        }
        sum += __shfl_xor_sync(0xFFFFFFFFu, sum, 1);
        sum += __shfl_xor_sync(0xFFFFFFFFu, sum, 2);
        if (tr == 0) rinv[row] = 1.0f / sum;
    }
    __syncthreads();

    {
        const int ty2 = tid >> 4;
        const int tx2 = tid & 15;
        float oa[4][4];
#pragma unroll
        for (int i = 0; i < 4; i++)
#pragma unroll
            for (int j = 0; j < 4; j++) oa[i][j] = 0.f;
#pragma unroll 4
        for (int k = 0; k < 256; k++) {
            float4 a  = *(const float4*)&S[k * 64 + ty2 * 4];
            float4 bb = *(const float4*)&Vs[k * 64 + tx2 * 4];
            float av[4] = {a.x, a.y, a.z, a.w};
            float bw[4] = {bb.x, bb.y, bb.z, bb.w};
#pragma unroll
            for (int i = 0; i < 4; i++)
#pragma unroll
                for (int j = 0; j < 4; j++)
                    oa[i][j] += av[i] * bw[j];
        }
#pragma unroll
        for (int i = 0; i < 4; i++) {
            int m = ty2 * 4 + i;
            float sc = rinv[m];
            float4 w = make_float4(oa[i][0]*sc, oa[i][1]*sc, oa[i][2]*sc, oa[i][3]*sc);
            *(float4*)(O + ((size_t)(b * Fdim + qb + m)) * Hdim + hd * DH + tx2 * 4) = w;
        }
    }
}

// ---------------- launch ----------------
extern "C" void kernel_launch(void* const* d_in, const int* in_sizes, int n_in,
                              void* d_out, int out_size)
{
    const float* x   = (const float*)d_in[0];
    const float* WE  = (const float*)d_in[1];
    const float* Wl  = (const float*)d_in[2];
    const float* bl  = (const float*)d_in[3];
    const float* Wg  = (const float*)d_in[4];
    const float* bg  = (const float*)d_in[5];
    const float* ipw = (const float*)d_in[6];
    const float* ipb = (const float*)d_in[7];
    const float* Wo  = (const float*)d_in[8];
    const float* bo  = (const float*)d_in[9];

    float* out    = (float*)d_out;
    float* x_time = out;
    float* x_out  = out + (size_t)Mrows * Hdim;

    float *h1, *q, *o, *gk, *gv;
    cudaGetSymbolAddress((void**)&h1, g_h1);
    cudaGetSymbolAddress((void**)&q,  g_q);
    cudaGetSymbolAddress((void**)&o,  g_o);
    cudaGetSymbolAddress((void**)&gk, g_k);
    cudaGetSymbolAddress((void**)&gv, g_v);

    cudaFuncSetAttribute(attn_kernel, cudaFuncAttributeMaxDynamicSharedMemorySize,
                         ATTN_SMEM_BYTES);

    dim3 blk(256);
    dim3 gg(Hdim / 128, Mrows / 128);   // (6, 256)

    // 1) h1 = x @ W_lin^T + b_lin           (K = 256)
    gemm_mma<0><<<gg, blk, G_SMEM_BYTES>>>(x, Wl, bl, h1, 256);
    // 2) x_time = gcn_mix(h1) @ W_gcn^T + b (K = 768, mix fused into A loads)
    gemm_mma<1><<<gg, blk, G_SMEM_BYTES>>>(h1, Wg, bg, x_time, Hdim);
    // 3) q = x_time @ Wq^T + bq
    gemm_mma<0><<<gg, blk, G_SMEM_BYTES>>>(x_time, ipw, ipb, q, Hdim);
    // 4) k/v projections (batch-independent)
    kv_kernel<<<dim3(Hdim / 4, 2), 256>>>(WE, ipw, ipb, gk, gv);
    // 5) fused attention
    attn_kernel<<<dim3(Fdim / 64, NHEAD, Bdim), 256, ATTN_SMEM_BYTES>>>(q, gk, gv, o);
    // 6) x_out = o @ out_proj_w^T + out_proj_b
    gemm_mma<0><<<gg, blk, G_SMEM_BYTES>>>(o, Wo, bo, x_out, Hdim);
}

// round 8
// speedup vs baseline: 2.0567x; 1.3762x over previous
#include <cuda_runtime.h>
#include <cuda_fp16.h>
#include <cstdint>
#include <cstddef>

#define Hdim  768
#define Fdim  512
#define Bdim  64
#define Mrows (Bdim * Fdim)       /* 32768 */
#define Vocab 256
#define NHEAD 12
#define DH    64

// ---------------- scratch (no allocations allowed) ----------------
__device__ float  g_h1[(size_t)Mrows * Hdim];
__device__ float  g_q [(size_t)Mrows * Hdim];
__device__ float  g_o [(size_t)Mrows * Hdim];
__device__ __half g_kh[NHEAD * Vocab * DH];   // [head][key][d]
__device__ __half g_kl[NHEAD * Vocab * DH];
__device__ __half g_vh[NHEAD * DH * Vocab];   // [head][d][key]
__device__ __half g_vl[NHEAD * DH * Vocab];

__device__ __forceinline__ uint32_t smem_u32(const void* p) {
    uint32_t r;
    asm("{ .reg .u64 t; cvta.to.shared.u64 t, %1; cvt.u32.u64 %0, t; }"
        : "=r"(r) : "l"(p));
    return r;
}
__device__ __forceinline__ void ldm_x4(uint32_t& r0, uint32_t& r1,
                                       uint32_t& r2, uint32_t& r3, uint32_t addr) {
    asm volatile("ldmatrix.sync.aligned.m8n8.x4.shared.b16 {%0,%1,%2,%3}, [%4];"
                 : "=r"(r0), "=r"(r1), "=r"(r2), "=r"(r3) : "r"(addr));
}
__device__ __forceinline__ void mma16816(float* d, const uint32_t* a,
                                         uint32_t b0, uint32_t b1) {
    asm volatile(
        "mma.sync.aligned.m16n8k16.row.col.f32.f16.f16.f32 "
        "{%0,%1,%2,%3}, {%4,%5,%6,%7}, {%8,%9}, {%0,%1,%2,%3};"
        : "+f"(d[0]), "+f"(d[1]), "+f"(d[2]), "+f"(d[3])
        : "r"(a[0]), "r"(a[1]), "r"(a[2]), "r"(a[3]), "r"(b0), "r"(b1));
}

// ================= HMMA GEMM (double-buffered): C = A*W^T + bias ==========
#define GSTRIDE 40
#define TILE_H  (128 * GSTRIDE)
#define GBUF_H  (4 * TILE_H)                   /* halves per buffer */
#define G2_SMEM_BYTES (2 * GBUF_H * 2)         /* 81920 B */

template <int MIX>
__device__ __forceinline__ void stage_load(const float* __restrict__ src,
                                           int row0, int K, int kc, int tid,
                                           float4 st[4])
{
    const int row = tid >> 1;
    const int seg = (tid & 1) << 4;
    const float* p = src + (size_t)(row0 + row) * K + kc + seg;
    st[0] = *(const float4*)(p + 0);
    st[1] = *(const float4*)(p + 4);
    st[2] = *(const float4*)(p + 8);
    st[3] = *(const float4*)(p + 12);
    if (MIX) {
        int f = (row0 + row) & (Fdim - 1);
        if ((unsigned)(f - 1) < 4u) {
            float s1 = (f == 1) ? 0.70710678118654752440f : 0.5f;
#pragma unroll
            for (int j = 0; j < 4; j++) {
                float4 pv = *(const float4*)(p - K + 4 * j);
                st[j].x = 0.5f * st[j].x + s1 * pv.x;
                st[j].y = 0.5f * st[j].y + s1 * pv.y;
                st[j].z = 0.5f * st[j].z + s1 * pv.z;
                st[j].w = 0.5f * st[j].w + s1 * pv.w;
            }
        }
    }
}

__device__ __forceinline__ void stage_store(const float4 st[4], __half* hi,
                                            __half* lo, int tid)
{
    const int row = tid >> 1;
    const int seg = (tid & 1) << 4;
    const float* f = (const float*)st;
    uint32_t hp[8], lp[8];
#pragma unroll
    for (int j = 0; j < 8; j++) {
        float a = f[2 * j], b = f[2 * j + 1];
        __half ha = __float2half_rn(a), hb = __float2half_rn(b);
        float la = a - __half2float(ha), lb = b - __half2float(hb);
        __half2 h2 = __halves2half2(ha, hb);
        __half2 l2 = __floats2half2_rn(la, lb);
        hp[j] = *(uint32_t*)&h2;
        lp[j] = *(uint32_t*)&l2;
    }
    uint32_t off = row * GSTRIDE + seg;
    *(uint4*)(hi + off)     = make_uint4(hp[0], hp[1], hp[2], hp[3]);
    *(uint4*)(hi + off + 8) = make_uint4(hp[4], hp[5], hp[6], hp[7]);
    *(uint4*)(lo + off)     = make_uint4(lp[0], lp[1], lp[2], lp[3]);
    *(uint4*)(lo + off + 8) = make_uint4(lp[4], lp[5], lp[6], lp[7]);
}

template <int MIX>
__global__ void __launch_bounds__(256)
gemm_mma(const float* __restrict__ A, const float* __restrict__ W,
         const float* __restrict__ bias, float* __restrict__ C, int K)
{
    extern __shared__ __align__(16) __half gsm[];
    const int tid = threadIdx.x;
    const int wid = tid >> 5;
    const int ln  = tid & 31;
    const int wm  = wid >> 2;
    const int wn  = wid & 3;
    const int m0  = blockIdx.y << 7;
    const int n0  = blockIdx.x << 7;

    const int lrow  = ln & 15;
    const int lcol8 = (ln >> 4) << 3;
    const uint32_t sb0 = smem_u32(gsm);

    float acc[4][4][4];
#pragma unroll
    for (int i = 0; i < 4; i++)
#pragma unroll
        for (int j = 0; j < 4; j++)
#pragma unroll
            for (int r = 0; r < 4; r++) acc[i][j][r] = 0.f;

    const int nchunk = K >> 5;
    float4 sa[4], sw[4];

    stage_load<MIX>(A, m0, K, 0, tid, sa);
    stage_load<0>  (W, n0, K, 0, tid, sw);
    stage_store(sa, gsm,              gsm + TILE_H,     tid);
    stage_store(sw, gsm + 2 * TILE_H, gsm + 3 * TILE_H, tid);
    __syncthreads();

    for (int c = 0; c < nchunk; c++) {
        if (c + 1 < nchunk) {
            stage_load<MIX>(A, m0, K, (c + 1) << 5, tid, sa);
            stage_load<0>  (W, n0, K, (c + 1) << 5, tid, sw);
        }
        const uint32_t bb = sb0 + (uint32_t)(c & 1) * (GBUF_H * 2);
        const uint32_t uAhi = bb, uAlo = bb + TILE_H * 2;
        const uint32_t uBhi = bb + 2 * TILE_H * 2, uBlo = bb + 3 * TILE_H * 2;
#pragma unroll
        for (int ks = 0; ks < 2; ks++) {
            const uint32_t cadd = (ks * 16 + lcol8) * 2;
            uint32_t ah[4][4], al[4][4], bh[2][4], bl[2][4];
#pragma unroll
            for (int tm = 0; tm < 4; tm++) {
                uint32_t off = ((wm * 64 + tm * 16 + lrow) * GSTRIDE) * 2 + cadd;
                ldm_x4(ah[tm][0], ah[tm][1], ah[tm][2], ah[tm][3], uAhi + off);
                ldm_x4(al[tm][0], al[tm][1], al[tm][2], al[tm][3], uAlo + off);
            }
#pragma unroll
            for (int pp = 0; pp < 2; pp++) {
                uint32_t off = ((wn * 32 + pp * 16 + lrow) * GSTRIDE) * 2 + cadd;
                ldm_x4(bh[pp][0], bh[pp][1], bh[pp][2], bh[pp][3], uBhi + off);
                ldm_x4(bl[pp][0], bl[pp][1], bl[pp][2], bl[pp][3], uBlo + off);
            }
#pragma unroll
            for (int tm = 0; tm < 4; tm++)
#pragma unroll
                for (int tn = 0; tn < 4; tn++) {
                    const int pp = tn >> 1, ii = tn & 1;
                    uint32_t b0h = bh[pp][ii], b1h = bh[pp][ii + 2];
                    uint32_t b0l = bl[pp][ii], b1l = bl[pp][ii + 2];
                    mma16816(acc[tm][tn], ah[tm], b0h, b1h);
                    mma16816(acc[tm][tn], ah[tm], b0l, b1l);
                    mma16816(acc[tm][tn], al[tm], b0h, b1h);
                }
        }
        if (c + 1 < nchunk) {
            __half* nb = gsm + (size_t)((c + 1) & 1) * GBUF_H;
            stage_store(sa, nb,              nb + TILE_H,     tid);
            stage_store(sw, nb + 2 * TILE_H, nb + 3 * TILE_H, tid);
        }
        __syncthreads();
    }

    const int g  = ln >> 2;
    const int c2 = (ln & 3) << 1;
#pragma unroll
    for (int tm = 0; tm < 4; tm++) {
#pragma unroll
        for (int tn = 0; tn < 4; tn++) {
            const int col = n0 + wn * 32 + tn * 8 + c2;
            const float b0 = bias[col], b1 = bias[col + 1];
            const int r0 = m0 + wm * 64 + tm * 16 + g;
            float2 v0 = make_float2(acc[tm][tn][0] + b0, acc[tm][tn][1] + b1);
            float2 v1 = make_float2(acc[tm][tn][2] + b0, acc[tm][tn][3] + b1);
            *(float2*)(C + (size_t)r0 * Hdim + col)       = v0;
            *(float2*)(C + (size_t)(r0 + 8) * Hdim + col) = v1;
        }
    }
}

// ---------------- K/V projection: ILP-blocked, emits fp16 hi/lo ----------
// grid(96, 2), block 512: 8 channels/block, h split in 2 halves + smem reduce
__global__ void __launch_bounds__(512)
kv_kernel2(const float* __restrict__ WE, const float* __restrict__ ipw,
           const float* __restrict__ ipb,
           __half* __restrict__ kh, __half* __restrict__ kl,
           __half* __restrict__ vh, __half* __restrict__ vl)
{
    __shared__ float part[2][8][Vocab];
    const int nb    = blockIdx.x << 3;
    const int which = blockIdx.y;
    const float* W  = ipw + (size_t)(which + 1) * Hdim * Hdim;
    const int grp   = threadIdx.x >> 8;
    const int vv    = threadIdx.x & 255;
    const int h0    = grp * (Hdim / 2);

    float a[8];
#pragma unroll
    for (int j = 0; j < 8; j++) a[j] = 0.f;
#pragma unroll 4
    for (int h = h0; h < h0 + Hdim / 2; h++) {
        float we = WE[h * Vocab + vv];
#pragma unroll
        for (int j = 0; j < 8; j++)
            a[j] += we * __ldg(W + (size_t)(nb + j) * Hdim + h);
    }
#pragma unroll
    for (int j = 0; j < 8; j++) part[grp][j][vv] = a[j];
    __syncthreads();
    if (grp == 0) {
#pragma unroll
        for (int j = 0; j < 8; j++) {
            int n = nb + j;
            float r = part[0][j][vv] + part[1][j][vv] + ipb[(which + 1) * Hdim + n];
            int head = n >> 6, d = n & 63;
            __half hi = __float2half_rn(r);
            __half lo = __float2half_rn(r - __half2float(hi));
            if (which == 0) {
                size_t o = ((size_t)head * Vocab + vv) * DH + d;   // [head][key][d]
                kh[o] = hi; kl[o] = lo;
            } else {
                size_t o = ((size_t)head * DH + d) * Vocab + vv;   // [head][d][key]
                vh[o] = hi; vl[o] = lo;
            }
        }
    }
}

// ---------------- fused HMMA attention ----------------
// grid(8, 12, 64), 512 threads. fp16 hi/lo 3-term split for QK and PV.
#define OFF64(r, c)  ((uint32_t)((r) * 128 + ((((c) >> 3) ^ ((r) & 7)) << 4) + (((c) & 7) << 1)))
#define OFF256(r, c) ((uint32_t)((r) * 512 + ((((c) >> 3) ^ ((r) & 7)) << 4) + (((c) & 7) << 1)))

#define QH_OFF   0
#define QL_OFF   8192
#define KH_OFF   16384
#define KL_OFF   49152
#define VH_OFF   81920
#define VL_OFF   114688
#define PH_OFF   147456
#define PL_OFF   180224
#define RMAX_OFF 212992
#define RSUM_OFF 215040
#define GMAX_OFF 217088
#define RINV_OFF 217344
#define ATTN2_SMEM 217600

__global__ void __launch_bounds__(512)
attn_mma(const float* __restrict__ Q,
         const __half* __restrict__ KHg, const __half* __restrict__ KLg,
         const __half* __restrict__ VHg, const __half* __restrict__ VLg,
         float* __restrict__ O)
{
    extern __shared__ __align__(16) char smc[];
    const uint32_t sb = smem_u32(smc);
    const int tid = threadIdx.x;
    const int wid = tid >> 5;
    const int ln  = tid & 31;
    const int lrow = ln & 15;
    const int lcol8 = (ln >> 4) << 3;
    const int g  = ln >> 2;
    const int c2 = (ln & 3) << 1;
    const int qb = blockIdx.x << 6;
    const int hd = blockIdx.y;
    const int b  = blockIdx.z;

    float* rmax = (float*)(smc + RMAX_OFF);
    float* rsum = (float*)(smc + RSUM_OFF);
    float* gmax = (float*)(smc + GMAX_OFF);
    float* rinv = (float*)(smc + RINV_OFF);

    // ---- fill: Q (fp32 -> hi/lo), K, V (pre-split halves, direct copies) ----
    {
        int m  = tid >> 3;
        int d8 = (tid & 7) << 3;
        const float* p = Q + ((size_t)(b * Fdim + qb + m)) * Hdim + hd * DH + d8;
        float4 v0 = *(const float4*)p;
        float4 v1 = *(const float4*)(p + 4);
        float f8[8] = {v0.x, v0.y, v0.z, v0.w, v1.x, v1.y, v1.z, v1.w};
        uint32_t hp[4], lp[4];
#pragma unroll
        for (int j = 0; j < 4; j++) {
            float a = f8[2 * j], bv = f8[2 * j + 1];
            __half ha = __float2half_rn(a), hb = __float2half_rn(bv);
            float la = a - __half2float(ha), lb = bv - __half2float(hb);
            __half2 h2 = __halves2half2(ha, hb);
            __half2 l2 = __floats2half2_rn(la, lb);
            hp[j] = *(uint32_t*)&h2;
            lp[j] = *(uint32_t*)&l2;
        }
        *(uint4*)(smc + QH_OFF + OFF64(m, d8)) = make_uint4(hp[0], hp[1], hp[2], hp[3]);
        *(uint4*)(smc + QL_OFF + OFF64(m, d8)) = make_uint4(lp[0], lp[1], lp[2], lp[3]);
    }
#pragma unroll
    for (int it = 0; it < 4; it++) {
        int idx = it * 512 + tid;                 // 0..2047
        int r = idx >> 3, c8 = (idx & 7) << 3;    // K: 256 rows x 8 groups
        size_t go = ((size_t)hd * Vocab + r) * DH + c8;
        *(uint4*)(smc + KH_OFF + OFF64(r, c8)) = *(const uint4*)(KHg + go);
        *(uint4*)(smc + KL_OFF + OFF64(r, c8)) = *(const uint4*)(KLg + go);
        int rv = idx >> 5, cv8 = (idx & 31) << 3; // V: 64 rows x 32 groups
        size_t gv = ((size_t)hd * DH + rv) * Vocab + cv8;
        *(uint4*)(smc + VH_OFF + OFF256(rv, cv8)) = *(const uint4*)(VHg + gv);
        *(uint4*)(smc + VL_OFF + OFF256(rv, cv8)) = *(const uint4*)(VLg + gv);
    }
    __syncthreads();

    // ---- phase 1: S = Q*K^T (M=64, N=256, K=64), warp grid 2m x 8n ----
    float acc[2][4][4];
#pragma unroll
    for (int i = 0; i < 2; i++)
#pragma unroll
        for (int j = 0; j < 4; j++)
#pragma unroll
            for (int r = 0; r < 4; r++) acc[i][j][r] = 0.f;
    {
        const int wm = wid >> 3, wn = wid & 7;
#pragma unroll
        for (int ks = 0; ks < 4; ks++) {
            const int kb = ks * 16 + lcol8;
            uint32_t ah[2][4], al[2][4], bh[2][4], bl[2][4];
#pragma unroll
            for (int tm = 0; tm < 2; tm++) {
                int r = wm * 32 + tm * 16 + lrow;
                ldm_x4(ah[tm][0], ah[tm][1], ah[tm][2], ah[tm][3], sb + QH_OFF + OFF64(r, kb));
                ldm_x4(al[tm][0], al[tm][1], al[tm][2], al[tm][3], sb + QL_OFF + OFF64(r, kb));
            }
#pragma unroll
            for (int pp = 0; pp < 2; pp++) {
                int r = wn * 32 + pp * 16 + lrow;
                ldm_x4(bh[pp][0], bh[pp][1], bh[pp][2], bh[pp][3], sb + KH_OFF + OFF64(r, kb));
                ldm_x4(bl[pp][0], bl[pp][1], bl[pp][2], bl[pp][3], sb + KL_OFF + OFF64(r, kb));
            }
#pragma unroll
            for (int tm = 0; tm < 2; tm++)
#pragma unroll
                for (int tn = 0; tn < 4; tn++) {
                    const int pp = tn >> 1, ii = tn & 1;
                    mma16816(acc[tm][tn], ah[tm], bh[pp][ii], bh[pp][ii + 2]);
                    mma16816(acc[tm][tn], ah[tm], bl[pp][ii], bl[pp][ii + 2]);
                    mma16816(acc[tm][tn], al[tm], bh[pp][ii], bh[pp][ii + 2]);
                }
        }
#pragma unroll
        for (int i = 0; i < 2; i++)
#pragma unroll
            for (int j = 0; j < 4; j++)
#pragma unroll
                for (int r = 0; r < 4; r++) acc[i][j][r] *= 0.125f;

        // ---- softmax (two-pass, cross-warp via smem) ----
#pragma unroll
        for (int tm = 0; tm < 2; tm++) {
            float m0 = -1e30f, m1 = -1e30f;
#pragma unroll
            for (int tn = 0; tn < 4; tn++) {
                m0 = fmaxf(m0, fmaxf(acc[tm][tn][0], acc[tm][tn][1]));
                m1 = fmaxf(m1, fmaxf(acc[tm][tn][2], acc[tm][tn][3]));
            }
            m0 = fmaxf(m0, __shfl_xor_sync(0xFFFFFFFFu, m0, 1));
            m0 = fmaxf(m0, __shfl_xor_sync(0xFFFFFFFFu, m0, 2));
            m1 = fmaxf(m1, __shfl_xor_sync(0xFFFFFFFFu, m1, 1));
            m1 = fmaxf(m1, __shfl_xor_sync(0xFFFFFFFFu, m1, 2));
            if ((ln & 3) == 0) {
                int r0 = wm * 32 + tm * 16 + g;
                rmax[wn * 64 + r0]     = m0;
                rmax[wn * 64 + r0 + 8] = m1;
            }
        }
        __syncthreads();
        if (tid < 64) {
            float mm = rmax[tid];
#pragma unroll
            for (int w = 1; w < 8; w++) mm = fmaxf(mm, rmax[w * 64 + tid]);
            gmax[tid] = mm;
        }
        __syncthreads();
#pragma unroll
        for (int tm = 0; tm < 2; tm++) {
            const int r0 = wm * 32 + tm * 16 + g, r1 = r0 + 8;
            const float gm0 = gmax[r0], gm1 = gmax[r1];
            float s0 = 0.f, s1 = 0.f;
#pragma unroll
            for (int tn = 0; tn < 4; tn++) {
                const int col = wn * 32 + tn * 8 + c2;
                float e0 = __expf(acc[tm][tn][0] - gm0);
                float e1 = __expf(acc[tm][tn][1] - gm0);
                float e2 = __expf(acc[tm][tn][2] - gm1);
                float e3 = __expf(acc[tm][tn][3] - gm1);
                s0 += e0 + e1; s1 += e2 + e3;
                __half h0 = __float2half_rn(e0), h1 = __float2half_rn(e1);
                __half h2 = __float2half_rn(e2), h3 = __float2half_rn(e3);
                __half2 hp0 = __halves2half2(h0, h1), hp1 = __halves2half2(h2, h3);
                __half2 lp0 = __floats2half2_rn(e0 - __half2float(h0), e1 - __half2float(h1));
                __half2 lp1 = __floats2half2_rn(e2 - __half2float(h2), e3 - __half2float(h3));
                *(uint32_t*)(smc + PH_OFF + OFF256(r0, col)) = *(uint32_t*)&hp0;
                *(uint32_t*)(smc + PH_OFF + OFF256(r1, col)) = *(uint32_t*)&hp1;
                *(uint32_t*)(smc + PL_OFF + OFF256(r0, col)) = *(uint32_t*)&lp0;
                *(uint32_t*)(smc + PL_OFF + OFF256(r1, col)) = *(uint32_t*)&lp1;
            }
            s0 += __shfl_xor_sync(0xFFFFFFFFu, s0, 1);
            s0 += __shfl_xor_sync(0xFFFFFFFFu, s0, 2);
            s1 += __shfl_xor_sync(0xFFFFFFFFu, s1, 1);
            s1 += __shfl_xor_sync(0xFFFFFFFFu, s1, 2);
            if ((ln & 3) == 0) {
                rsum[wn * 64 + r0] = s0;
                rsum[wn * 64 + r1] = s1;
            }
        }
        __syncthreads();
        if (tid < 64) {
            float s = 0.f;
#pragma unroll
            for (int w = 0; w < 8; w++) s += rsum[w * 64 + tid];
            rinv[tid] = 1.0f / s;
        }
        __syncthreads();
    }

    // ---- phase 2: O = P*V (M=64, N=64, K=256), warp grid 4m x 4n ----
    {
        const int wm2 = wid >> 2, wn2 = wid & 3;
        float a2[2][4];
#pragma unroll
        for (int j = 0; j < 2; j++)
#pragma unroll
            for (int r = 0; r < 4; r++) a2[j][r] = 0.f;
#pragma unroll 4
        for (int ks = 0; ks < 16; ks++) {
            const int kb = ks * 16 + lcol8;
            uint32_t pa[4], pl4[4], vb[4], vl4[4];
            const int ra = wm2 * 16 + lrow;
            ldm_x4(pa[0], pa[1], pa[2], pa[3],   sb + PH_OFF + OFF256(ra, kb));
            ldm_x4(pl4[0], pl4[1], pl4[2], pl4[3], sb + PL_OFF + OFF256(ra, kb));
            const int rb = wn2 * 16 + lrow;
            ldm_x4(vb[0], vb[1], vb[2], vb[3],   sb + VH_OFF + OFF256(rb, kb));
            ldm_x4(vl4[0], vl4[1], vl4[2], vl4[3], sb + VL_OFF + OFF256(rb, kb));
#pragma unroll
            for (int tn = 0; tn < 2; tn++) {
                mma16816(a2[tn], pa,  vb[tn],  vb[tn + 2]);
                mma16816(a2[tn], pa,  vl4[tn], vl4[tn + 2]);
                mma16816(a2[tn], pl4, vb[tn],  vb[tn + 2]);
            }
        }
#pragma unroll
        for (int tn = 0; tn < 2; tn++) {
            const int col = hd * DH + wn2 * 16 + tn * 8 + c2;
            const int r0 = wm2 * 16 + g;
            const float iv0 = rinv[r0], iv1 = rinv[r0 + 8];
            float2 v0 = make_float2(a2[tn][0] * iv0, a2[tn][1] * iv0);
            float2 v1 = make_float2(a2[tn][2] * iv1, a2[tn][3] * iv1);
            *(float2*)(O + ((size_t)(b * Fdim + qb + r0)) * Hdim + col)     = v0;
            *(float2*)(O + ((size_t)(b * Fdim + qb + r0 + 8)) * Hdim + col) = v1;
        }
    }
}

// ---------------- launch ----------------
extern "C" void kernel_launch(void* const* d_in, const int* in_sizes, int n_in,
                              void* d_out, int out_size)
{
    const float* x   = (const float*)d_in[0];
    const float* WE  = (const float*)d_in[1];
    const float* Wl  = (const float*)d_in[2];
    const float* bl  = (const float*)d_in[3];
    const float* Wg  = (const float*)d_in[4];
    const float* bg  = (const float*)d_in[5];
    const float* ipw = (const float*)d_in[6];
    const float* ipb = (const float*)d_in[7];
    const float* Wo  = (const float*)d_in[8];
    const float* bo  = (const float*)d_in[9];

    float* out    = (float*)d_out;
    float* x_time = out;
    float* x_out  = out + (size_t)Mrows * Hdim;

    float *h1, *q, *o;
    __half *kh, *kl, *vh, *vl;
    cudaGetSymbolAddress((void**)&h1, g_h1);
    cudaGetSymbolAddress((void**)&q,  g_q);
    cudaGetSymbolAddress((void**)&o,  g_o);
    cudaGetSymbolAddress((void**)&kh, g_kh);
    cudaGetSymbolAddress((void**)&kl, g_kl);
    cudaGetSymbolAddress((void**)&vh, g_vh);
    cudaGetSymbolAddress((void**)&vl, g_vl);

    cudaFuncSetAttribute(gemm_mma<0>, cudaFuncAttributeMaxDynamicSharedMemorySize,
                         G2_SMEM_BYTES);
    cudaFuncSetAttribute(gemm_mma<1>, cudaFuncAttributeMaxDynamicSharedMemorySize,
                         G2_SMEM_BYTES);
    cudaFuncSetAttribute(attn_mma, cudaFuncAttributeMaxDynamicSharedMemorySize,
                         ATTN2_SMEM);

    dim3 blk(256);
    dim3 gg(Hdim / 128, Mrows / 128);   // (6, 256)

    // 1) h1 = x @ W_lin^T + b_lin           (K = 256)
    gemm_mma<0><<<gg, blk, G2_SMEM_BYTES>>>(x, Wl, bl, h1, 256);
    // 2) x_time = gcn_mix(h1) @ W_gcn^T + b (K = 768)
    gemm_mma<1><<<gg, blk, G2_SMEM_BYTES>>>(h1, Wg, bg, x_time, Hdim);
    // 3) q = x_time @ Wq^T + bq
    gemm_mma<0><<<gg, blk, G2_SMEM_BYTES>>>(x_time, ipw, ipb, q, Hdim);
    // 4) k/v projections -> fp16 hi/lo, attention layouts
    kv_kernel2<<<dim3(Hdim / 8, 2), 512>>>(WE, ipw, ipb, kh, kl, vh, vl);
    // 5) fused HMMA attention
    attn_mma<<<dim3(Fdim / 64, NHEAD, Bdim), 512, ATTN2_SMEM>>>(q, kh, kl, vh, vl, o);
    // 6) x_out = o @ out_proj_w^T + out_proj_b
    gemm_mma<0><<<gg, blk, G2_SMEM_BYTES>>>(o, Wo, bo, x_out, Hdim);
}

// round 11
// speedup vs baseline: 3.0604x; 1.4880x over previous
#include <cuda_runtime.h>
#include <cuda_fp16.h>
#include <cstdint>
#include <cstddef>

#define Hdim  768
#define Fdim  512
#define Bdim  64
#define Mrows (Bdim * Fdim)       /* 32768 */
#define Vocab 256
#define NHEAD 12
#define DH    64

// ---------------- scratch (no allocations allowed) ----------------
__device__ float  g_q  [(size_t)Mrows * Hdim];
__device__ float  g_o  [(size_t)Mrows * Hdim];
__device__ float  g_wlt [256 * Hdim];      // Wl^T (256,768)
__device__ float  g_wglt[256 * Hdim];      // (Wg*Wl)^T (256,768)
__device__ float  g_wgl [Hdim * 256];      // Wg*Wl (768,256)
__device__ float  g_wql [Hdim * 256];      // Wq*Wg*Wl (768,256)
__device__ float  g_u1 [Hdim];
__device__ float  g_v1 [Hdim];
__device__ float  g_v0 [Hdim];
__device__ float  g_zero[Hdim];            // stays zero (never written)
__device__ __half g_kh[NHEAD * Vocab * DH];   // [head][key][d]
__device__ __half g_kl[NHEAD * Vocab * DH];
__device__ __half g_vh[NHEAD * DH * Vocab];   // [head][d][key]
__device__ __half g_vl[NHEAD * DH * Vocab];

__device__ __forceinline__ uint32_t smem_u32(const void* p) {
    uint32_t r;
    asm("{ .reg .u64 t; cvta.to.shared.u64 t, %1; cvt.u32.u64 %0, t; }"
        : "=r"(r) : "l"(p));
    return r;
}
__device__ __forceinline__ void ldm_x4(uint32_t& r0, uint32_t& r1,
                                       uint32_t& r2, uint32_t& r3, uint32_t addr) {
    asm volatile("ldmatrix.sync.aligned.m8n8.x4.shared.b16 {%0,%1,%2,%3}, [%4];"
                 : "=r"(r0), "=r"(r1), "=r"(r2), "=r"(r3) : "r"(addr));
}
__device__ __forceinline__ void mma16816(float* d, const uint32_t* a,
                                         uint32_t b0, uint32_t b1) {
    asm volatile(
        "mma.sync.aligned.m16n8k16.row.col.f32.f16.f16.f32 "
        "{%0,%1,%2,%3}, {%4,%5,%6,%7}, {%8,%9}, {%0,%1,%2,%3};"
        : "+f"(d[0]), "+f"(d[1]), "+f"(d[2]), "+f"(d[3])
        : "r"(a[0]), "r"(a[1]), "r"(a[2]), "r"(a[3]), "r"(b0), "r"(b1));
}

// ================= HMMA GEMM (double-buffered): C = A*W^T + bias ==========
// BMODE 0: +b0v[col].  BMODE 1: +b0v[col] + m_f*b1v[col], m_f=1.2071 iff (row&511)==1
#define GSTRIDE 40
#define TILE_H  (128 * GSTRIDE)
#define GBUF_H  (4 * TILE_H)                   /* halves per buffer */
#define G2_SMEM_BYTES (2 * GBUF_H * 2)         /* 81920 B */
#define MF_F1 1.20710678118654752440f

template <int MIX>
__device__ __forceinline__ void stage_load(const float* __restrict__ src,
                                           int row0, int K, int kc, int tid,
                                           float4 st[4])
{
    const int row = tid >> 1;
    const int seg = (tid & 1) << 4;
    const float* p = src + (size_t)(row0 + row) * K + kc + seg;
    st[0] = *(const float4*)(p + 0);
    st[1] = *(const float4*)(p + 4);
    st[2] = *(const float4*)(p + 8);
    st[3] = *(const float4*)(p + 12);
    if (MIX) {
        int f = (row0 + row) & (Fdim - 1);
        if ((unsigned)(f - 1) < 4u) {
            float s1 = (f == 1) ? 0.70710678118654752440f : 0.5f;
#pragma unroll
            for (int j = 0; j < 4; j++) {
                float4 pv = *(const float4*)(p - K + 4 * j);
                st[j].x = 0.5f * st[j].x + s1 * pv.x;
                st[j].y = 0.5f * st[j].y + s1 * pv.y;
                st[j].z = 0.5f * st[j].z + s1 * pv.z;
                st[j].w = 0.5f * st[j].w + s1 * pv.w;
            }
        }
    }
}

__device__ __forceinline__ void stage_store(const float4 st[4], __half* hi,
                                            __half* lo, int tid)
{
    const int row = tid >> 1;
    const int seg = (tid & 1) << 4;
    const float* f = (const float*)st;
    uint32_t hp[8], lp[8];
#pragma unroll
    for (int j = 0; j < 8; j++) {
        float a = f[2 * j], b = f[2 * j + 1];
        __half ha = __float2half_rn(a), hb = __float2half_rn(b);
        float la = a - __half2float(ha), lb = b - __half2float(hb);
        __half2 h2 = __halves2half2(ha, hb);
        __half2 l2 = __floats2half2_rn(la, lb);
        hp[j] = *(uint32_t*)&h2;
        lp[j] = *(uint32_t*)&l2;
    }
    uint32_t off = row * GSTRIDE + seg;
    *(uint4*)(hi + off)     = make_uint4(hp[0], hp[1], hp[2], hp[3]);
    *(uint4*)(hi + off + 8) = make_uint4(hp[4], hp[5], hp[6], hp[7]);
    *(uint4*)(lo + off)     = make_uint4(lp[0], lp[1], lp[2], lp[3]);
    *(uint4*)(lo + off + 8) = make_uint4(lp[4], lp[5], lp[6], lp[7]);
}

template <int MIX, int BMODE>
__global__ void __launch_bounds__(256)
gemm_mma(const float* __restrict__ A, const float* __restrict__ W,
         const float* __restrict__ b0v, const float* __restrict__ b1v,
         float* __restrict__ C, int K, int ldc)
{
    extern __shared__ __align__(16) __half gsm[];
    const int tid = threadIdx.x;
    const int wid = tid >> 5;
    const int ln  = tid & 31;
    const int wm  = wid >> 2;
    const int wn  = wid & 3;
    const int m0  = blockIdx.y << 7;
    const int n0  = blockIdx.x << 7;

    const int lrow  = ln & 15;
    const int lcol8 = (ln >> 4) << 3;
    const uint32_t sb0 = smem_u32(gsm);

    float acc[4][4][4];
#pragma unroll
    for (int i = 0; i < 4; i++)
#pragma unroll
        for (int j = 0; j < 4; j++)
#pragma unroll
            for (int r = 0; r < 4; r++) acc[i][j][r] = 0.f;

    const int nchunk = K >> 5;
    float4 sa[4], sw[4];

    stage_load<MIX>(A, m0, K, 0, tid, sa);
    stage_load<0>  (W, n0, K, 0, tid, sw);
    stage_store(sa, gsm,              gsm + TILE_H,     tid);
    stage_store(sw, gsm + 2 * TILE_H, gsm + 3 * TILE_H, tid);
    __syncthreads();

    for (int c = 0; c < nchunk; c++) {
        if (c + 1 < nchunk) {
            stage_load<MIX>(A, m0, K, (c + 1) << 5, tid, sa);
            stage_load<0>  (W, n0, K, (c + 1) << 5, tid, sw);
        }
        const uint32_t bb = sb0 + (uint32_t)(c & 1) * (GBUF_H * 2);
        const uint32_t uAhi = bb, uAlo = bb + TILE_H * 2;
        const uint32_t uBhi = bb + 2 * TILE_H * 2, uBlo = bb + 3 * TILE_H * 2;
#pragma unroll
        for (int ks = 0; ks < 2; ks++) {
            const uint32_t cadd = (ks * 16 + lcol8) * 2;
            uint32_t ah[4][4], al[4][4], bh[2][4], bl[2][4];
#pragma unroll
            for (int tm = 0; tm < 4; tm++) {
                uint32_t off = ((wm * 64 + tm * 16 + lrow) * GSTRIDE) * 2 + cadd;
                ldm_x4(ah[tm][0], ah[tm][1], ah[tm][2], ah[tm][3], uAhi + off);
                ldm_x4(al[tm][0], al[tm][1], al[tm][2], al[tm][3], uAlo + off);
            }
#pragma unroll
            for (int pp = 0; pp < 2; pp++) {
                uint32_t off = ((wn * 32 + pp * 16 + lrow) * GSTRIDE) * 2 + cadd;
                ldm_x4(bh[pp][0], bh[pp][1], bh[pp][2], bh[pp][3], uBhi + off);
                ldm_x4(bl[pp][0], bl[pp][1], bl[pp][2], bl[pp][3], uBlo + off);
            }
#pragma unroll
            for (int tm = 0; tm < 4; tm++)
#pragma unroll
                for (int tn = 0; tn < 4; tn++) {
                    const int pp = tn >> 1, ii = tn & 1;
                    uint32_t b0h = bh[pp][ii], b1h = bh[pp][ii + 2];
                    uint32_t b0l = bl[pp][ii], b1l = bl[pp][ii + 2];
                    mma16816(acc[tm][tn], ah[tm], b0h, b1h);
                    mma16816(acc[tm][tn], ah[tm], b0l, b1l);
                    mma16816(acc[tm][tn], al[tm], b0h, b1h);
                }
        }
        if (c + 1 < nchunk) {
            __half* nb = gsm + (size_t)((c + 1) & 1) * GBUF_H;
            stage_store(sa, nb,              nb + TILE_H,     tid);
            stage_store(sw, nb + 2 * TILE_H, nb + 3 * TILE_H, tid);
        }
        __syncthreads();
    }

    const int g  = ln >> 2;
    const int c2 = (ln & 3) << 1;
#pragma unroll
    for (int tm = 0; tm < 4; tm++) {
#pragma unroll
        for (int tn = 0; tn < 4; tn++) {
            const int col = n0 + wn * 32 + tn * 8 + c2;
            const int r0 = m0 + wm * 64 + tm * 16 + g;
            float bA0, bA1, bB0, bB1;     // biases for row r0 and row r0+8
            if (BMODE == 0) {
                bA0 = bB0 = b0v[col];
                bA1 = bB1 = b0v[col + 1];
            } else {
                const float u0a = b0v[col], u0b = b0v[col + 1];
                const float u1a = b1v[col], u1b = b1v[col + 1];
                const float mf0 = (((r0)     & (Fdim - 1)) == 1) ? MF_F1 : 1.0f;
                const float mf1 = (((r0 + 8) & (Fdim - 1)) == 1) ? MF_F1 : 1.0f;
                bA0 = u0a + mf0 * u1a; bA1 = u0b + mf0 * u1b;
                bB0 = u0a + mf1 * u1a; bB1 = u0b + mf1 * u1b;
            }
            float2 v0 = make_float2(acc[tm][tn][0] + bA0, acc[tm][tn][1] + bA1);
            float2 v1 = make_float2(acc[tm][tn][2] + bB0, acc[tm][tn][3] + bB1);
            *(float2*)(C + (size_t)r0 * ldc + col)       = v0;
            *(float2*)(C + (size_t)(r0 + 8) * ldc + col) = v1;
        }
    }
}

// ---------------- tiled transpose: out(C,R) = in(R,C)^T ----------------
__global__ void transpose_k(const float* __restrict__ in, float* __restrict__ out,
                            int R, int Ccol)
{
    __shared__ float t[32][33];
    int x = blockIdx.x * 32 + threadIdx.x;
    int y = blockIdx.y * 32 + threadIdx.y;
#pragma unroll
    for (int i = 0; i < 32; i += 8)
        if (y + i < R && x < Ccol) t[threadIdx.y + i][threadIdx.x] = in[(size_t)(y + i) * Ccol + x];
    __syncthreads();
    x = blockIdx.y * 32 + threadIdx.x;
    y = blockIdx.x * 32 + threadIdx.y;
#pragma unroll
    for (int i = 0; i < 32; i += 8)
        if (y + i < Ccol && x < R) out[(size_t)(y + i) * R + x] = t[threadIdx.x][threadIdx.y + i];
}

// ---------------- matvec: y = A(N,K) @ x + c ----------------
__global__ void matvec_k(const float* __restrict__ A, const float* __restrict__ x,
                         const float* __restrict__ c, float* __restrict__ y,
                         int N, int K)
{
    int r  = blockIdx.x * (blockDim.x >> 5) + (threadIdx.x >> 5);
    int ln = threadIdx.x & 31;
    if (r >= N) return;
    float s = 0.f;
    for (int j = ln; j < K; j += 32) s += A[(size_t)r * K + j] * x[j];
#pragma unroll
    for (int o = 16; o; o >>= 1) s += __shfl_xor_sync(0xFFFFFFFFu, s, o);
    if (ln == 0) y[r] = s + c[r];
}

// ---------------- K/V projection: 4 channels/block (grid-limit fix) ------
__global__ void __launch_bounds__(512)
kv_kernel2(const float* __restrict__ WE, const float* __restrict__ ipw,
           const float* __restrict__ ipb,
           __half* __restrict__ kh, __half* __restrict__ kl,
           __half* __restrict__ vh, __half* __restrict__ vl)
{
    __shared__ float part[2][4][Vocab];
    const int nb    = blockIdx.x << 2;
    const int which = blockIdx.y;
    const float* W  = ipw + (size_t)(which + 1) * Hdim * Hdim;
    const int grp   = threadIdx.x >> 8;
    const int vv    = threadIdx.x & 255;
    const int h0    = grp * (Hdim / 2);

    float a[4];
#pragma unroll
    for (int j = 0; j < 4; j++) a[j] = 0.f;
#pragma unroll 4
    for (int h = h0; h < h0 + Hdim / 2; h++) {
        float we = WE[h * Vocab + vv];
#pragma unroll
        for (int j = 0; j < 4; j++)
            a[j] += we * __ldg(W + (size_t)(nb + j) * Hdim + h);
    }
#pragma unroll
    for (int j = 0; j < 4; j++) part[grp][j][vv] = a[j];
    __syncthreads();
    if (grp == 0) {
#pragma unroll
        for (int j = 0; j < 4; j++) {
            int n = nb + j;
            float r = part[0][j][vv] + part[1][j][vv] + ipb[(which + 1) * Hdim + n];
            int head = n >> 6, d = n & 63;
            __half hi = __float2half_rn(r);
            __half lo = __float2half_rn(r - __half2float(hi));
            if (which == 0) {
                size_t o = ((size_t)head * Vocab + vv) * DH + d;   // [head][key][d]
                kh[o] = hi; kl[o] = lo;
            } else {
                size_t o = ((size_t)head * DH + d) * Vocab + vv;   // [head][d][key]
                vh[o] = hi; vl[o] = lo;
            }
        }
    }
}

// ---------------- fused HMMA attention ----------------
#define OFF64(r, c)  ((uint32_t)((r) * 128 + ((((c) >> 3) ^ ((r) & 7)) << 4) + (((c) & 7) << 1)))
#define OFF256(r, c) ((uint32_t)((r) * 512 + ((((c) >> 3) ^ ((r) & 7)) << 4) + (((c) & 7) << 1)))

#define QH_OFF   0
#define QL_OFF   8192
#define KH_OFF   16384
#define KL_OFF   49152
#define VH_OFF   81920
#define VL_OFF   114688
#define PH_OFF   147456
#define PL_OFF   180224
#define RMAX_OFF 212992
#define RSUM_OFF 215040
#define GMAX_OFF 217088
#define RINV_OFF 217344
#define ATTN2_SMEM 217600

__global__ void __launch_bounds__(512)
attn_mma(const float* __restrict__ Q,
         const __half* __restrict__ KHg, const __half* __restrict__ KLg,
         const __half* __restrict__ VHg, const __half* __restrict__ VLg,
         float* __restrict__ O)
{
    extern __shared__ __align__(16) char smc[];
    const uint32_t sb = smem_u32(smc);
    const int tid = threadIdx.x;
    const int wid = tid >> 5;
    const int ln  = tid & 31;
    const int lrow = ln & 15;
    const int lcol8 = (ln >> 4) << 3;
    const int g  = ln >> 2;
    const int c2 = (ln & 3) << 1;
    const int qb = blockIdx.x << 6;
    const int hd = blockIdx.y;
    const int b  = blockIdx.z;

    float* rmax = (float*)(smc + RMAX_OFF);
    float* rsum = (float*)(smc + RSUM_OFF);
    float* gmax = (float*)(smc + GMAX_OFF);
    float* rinv = (float*)(smc + RINV_OFF);

    {
        int m  = tid >> 3;
        int d8 = (tid & 7) << 3;
        const float* p = Q + ((size_t)(b * Fdim + qb + m)) * Hdim + hd * DH + d8;
        float4 v0 = *(const float4*)p;
        float4 v1 = *(const float4*)(p + 4);
        float f8[8] = {v0.x, v0.y, v0.z, v0.w, v1.x, v1.y, v1.z, v1.w};
        uint32_t hp[4], lp[4];
#pragma unroll
        for (int j = 0; j < 4; j++) {
            float a = f8[2 * j], bv = f8[2 * j + 1];
            __half ha = __float2half_rn(a), hb = __float2half_rn(bv);
            float la = a - __half2float(ha), lb = bv - __half2float(hb);
            __half2 h2 = __halves2half2(ha, hb);
            __half2 l2 = __floats2half2_rn(la, lb);
            hp[j] = *(uint32_t*)&h2;
            lp[j] = *(uint32_t*)&l2;
        }
        *(uint4*)(smc + QH_OFF + OFF64(m, d8)) = make_uint4(hp[0], hp[1], hp[2], hp[3]);
        *(uint4*)(smc + QL_OFF + OFF64(m, d8)) = make_uint4(lp[0], lp[1], lp[2], lp[3]);
    }
#pragma unroll
    for (int it = 0; it < 4; it++) {
        int idx = it * 512 + tid;
        int r = idx >> 3, c8 = (idx & 7) << 3;
        size_t go = ((size_t)hd * Vocab + r) * DH + c8;
        *(uint4*)(smc + KH_OFF + OFF64(r, c8)) = *(const uint4*)(KHg + go);
        *(uint4*)(smc + KL_OFF + OFF64(r, c8)) = *(const uint4*)(KLg + go);
        int rv = idx >> 5, cv8 = (idx & 31) << 3;
        size_t gv = ((size_t)hd * DH + rv) * Vocab + cv8;
        *(uint4*)(smc + VH_OFF + OFF256(rv, cv8)) = *(const uint4*)(VHg + gv);
        *(uint4*)(smc + VL_OFF + OFF256(rv, cv8)) = *(const uint4*)(VLg + gv);
    }
    __syncthreads();

    float acc[2][4][4];
#pragma unroll
    for (int i = 0; i < 2; i++)
#pragma unroll
        for (int j = 0; j < 4; j++)
#pragma unroll
            for (int r = 0; r < 4; r++) acc[i][j][r] = 0.f;
    {
        const int wm = wid >> 3, wn = wid & 7;
#pragma unroll
        for (int ks = 0; ks < 4; ks++) {
            const int kb = ks * 16 + lcol8;
            uint32_t ah[2][4], al[2][4], bh[2][4], bl[2][4];
#pragma unroll
            for (int tm = 0; tm < 2; tm++) {
                int r = wm * 32 + tm * 16 + lrow;
                ldm_x4(ah[tm][0], ah[tm][1], ah[tm][2], ah[tm][3], sb + QH_OFF + OFF64(r, kb));
                ldm_x4(al[tm][0], al[tm][1], al[tm][2], al[tm][3], sb + QL_OFF + OFF64(r, kb));
            }
#pragma unroll
            for (int pp = 0; pp < 2; pp++) {
                int r = wn * 32 + pp * 16 + lrow;
                ldm_x4(bh[pp][0], bh[pp][1], bh[pp][2], bh[pp][3], sb + KH_OFF + OFF64(r, kb));
                ldm_x4(bl[pp][0], bl[pp][1], bl[pp][2], bl[pp][3], sb + KL_OFF + OFF64(r, kb));
            }
#pragma unroll
            for (int tm = 0; tm < 2; tm++)
#pragma unroll
                for (int tn = 0; tn < 4; tn++) {
                    const int pp = tn >> 1, ii = tn & 1;
                    mma16816(acc[tm][tn], ah[tm], bh[pp][ii], bh[pp][ii + 2]);
                    mma16816(acc[tm][tn], ah[tm], bl[pp][ii], bl[pp][ii + 2]);
                    mma16816(acc[tm][tn], al[tm], bh[pp][ii], bh[pp][ii + 2]);
                }
        }
#pragma unroll
        for (int i = 0; i < 2; i++)
#pragma unroll
            for (int j = 0; j < 4; j++)
#pragma unroll
                for (int r = 0; r < 4; r++) acc[i][j][r] *= 0.125f;

#pragma unroll
        for (int tm = 0; tm < 2; tm++) {
            float m0 = -1e30f, m1 = -1e30f;
#pragma unroll
            for (int tn = 0; tn < 4; tn++) {
                m0 = fmaxf(m0, fmaxf(acc[tm][tn][0], acc[tm][tn][1]));
                m1 = fmaxf(m1, fmaxf(acc[tm][tn][2], acc[tm][tn][3]));
            }
            m0 = fmaxf(m0, __shfl_xor_sync(0xFFFFFFFFu, m0, 1));
            m0 = fmaxf(m0, __shfl_xor_sync(0xFFFFFFFFu, m0, 2));
            m1 = fmaxf(m1, __shfl_xor_sync(0xFFFFFFFFu, m1, 1));
            m1 = fmaxf(m1, __shfl_xor_sync(0xFFFFFFFFu, m1, 2));
            if ((ln & 3) == 0) {
                int r0 = wm * 32 + tm * 16 + g;
                rmax[wn * 64 + r0]     = m0;
                rmax[wn * 64 + r0 + 8] = m1;
            }
        }
        __syncthreads();
        if (tid < 64) {
            float mm = rmax[tid];
#pragma unroll
            for (int w = 1; w < 8; w++) mm = fmaxf(mm, rmax[w * 64 + tid]);
            gmax[tid] = mm;
        }
        __syncthreads();
#pragma unroll
        for (int tm = 0; tm < 2; tm++) {
            const int r0 = wm * 32 + tm * 16 + g, r1 = r0 + 8;
            const float gm0 = gmax[r0], gm1 = gmax[r1];
            float s0 = 0.f, s1 = 0.f;
#pragma unroll
            for (int tn = 0; tn < 4; tn++) {
                const int col = wn * 32 + tn * 8 + c2;
                float e0 = __expf(acc[tm][tn][0] - gm0);
                float e1 = __expf(acc[tm][tn][1] - gm0);
                float e2 = __expf(acc[tm][tn][2] - gm1);
                float e3 = __expf(acc[tm][tn][3] - gm1);
                s0 += e0 + e1; s1 += e2 + e3;
                __half h0 = __float2half_rn(e0), h1 = __float2half_rn(e1);
                __half h2 = __float2half_rn(e2), h3 = __float2half_rn(e3);
                __half2 hp0 = __halves2half2(h0, h1), hp1 = __halves2half2(h2, h3);
                __half2 lp0 = __floats2half2_rn(e0 - __half2float(h0), e1 - __half2float(h1));
                __half2 lp1 = __floats2half2_rn(e2 - __half2float(h2), e3 - __half2float(h3));
                *(uint32_t*)(smc + PH_OFF + OFF256(r0, col)) = *(uint32_t*)&hp0;
                *(uint32_t*)(smc + PH_OFF + OFF256(r1, col)) = *(uint32_t*)&hp1;
                *(uint32_t*)(smc + PL_OFF + OFF256(r0, col)) = *(uint32_t*)&lp0;
                *(uint32_t*)(smc + PL_OFF + OFF256(r1, col)) = *(uint32_t*)&lp1;
            }
            s0 += __shfl_xor_sync(0xFFFFFFFFu, s0, 1);
            s0 += __shfl_xor_sync(0xFFFFFFFFu, s0, 2);
            s1 += __shfl_xor_sync(0xFFFFFFFFu, s1, 1);
            s1 += __shfl_xor_sync(0xFFFFFFFFu, s1, 2);
            if ((ln & 3) == 0) {
                rsum[wn * 64 + r0] = s0;
                rsum[wn * 64 + r1] = s1;
            }
        }
        __syncthreads();
        if (tid < 64) {
            float s = 0.f;
#pragma unroll
            for (int w = 0; w < 8; w++) s += rsum[w * 64 + tid];
            rinv[tid] = 1.0f / s;
        }
        __syncthreads();
    }

    {
        const int wm2 = wid >> 2, wn2 = wid & 3;
        float a2[2][4];
#pragma unroll
        for (int j = 0; j < 2; j++)
#pragma unroll
            for (int r = 0; r < 4; r++) a2[j][r] = 0.f;
#pragma unroll 4
        for (int ks = 0; ks < 16; ks++) {
            const int kb = ks * 16 + lcol8;
            uint32_t pa[4], pl4[4], vb[4], vl4[4];
            const int ra = wm2 * 16 + lrow;
            ldm_x4(pa[0], pa[1], pa[2], pa[3],   sb + PH_OFF + OFF256(ra, kb));
            ldm_x4(pl4[0], pl4[1], pl4[2], pl4[3], sb + PL_OFF + OFF256(ra, kb));
            const int rb = wn2 * 16 + lrow;
            ldm_x4(vb[0], vb[1], vb[2], vb[3],   sb + VH_OFF + OFF256(rb, kb));
            ldm_x4(vl4[0], vl4[1], vl4[2], vl4[3], sb + VL_OFF + OFF256(rb, kb));
#pragma unroll
            for (int tn = 0; tn < 2; tn++) {
                mma16816(a2[tn], pa,  vb[tn],  vb[tn + 2]);
                mma16816(a2[tn], pa,  vl4[tn], vl4[tn + 2]);
                mma16816(a2[tn], pl4, vb[tn],  vb[tn + 2]);
            }
        }
#pragma unroll
        for (int tn = 0; tn < 2; tn++) {
            const int col = hd * DH + wn2 * 16 + tn * 8 + c2;
            const int r0 = wm2 * 16 + g;
            const float iv0 = rinv[r0], iv1 = rinv[r0 + 8];
            float2 v0 = make_float2(a2[tn][0] * iv0, a2[tn][1] * iv0);
            float2 v1 = make_float2(a2[tn][2] * iv1, a2[tn][3] * iv1);
            *(float2*)(O + ((size_t)(b * Fdim + qb + r0)) * Hdim + col)     = v0;
            *(float2*)(O + ((size_t)(b * Fdim + qb + r0 + 8)) * Hdim + col) = v1;
        }
    }
}

// ---------------- launch ----------------
extern "C" void kernel_launch(void* const* d_in, const int* in_sizes, int n_in,
                              void* d_out, int out_size)
{
    const float* x   = (const float*)d_in[0];
    const float* WE  = (const float*)d_in[1];
    const float* Wl  = (const float*)d_in[2];
    const float* bl  = (const float*)d_in[3];
    const float* Wg  = (const float*)d_in[4];
    const float* bg  = (const float*)d_in[5];
    const float* ipw = (const float*)d_in[6];
    const float* ipb = (const float*)d_in[7];
    const float* Wo  = (const float*)d_in[8];
    const float* bo  = (const float*)d_in[9];

    float* out    = (float*)d_out;
    float* x_time = out;
    float* x_out  = out + (size_t)Mrows * Hdim;

    float *q, *o, *wlt, *wglt, *wgl, *wql, *u1, *v1, *v0, *zero;
    __half *kh, *kl, *vh, *vl;
    cudaGetSymbolAddress((void**)&q,    g_q);
    cudaGetSymbolAddress((void**)&o,    g_o);
    cudaGetSymbolAddress((void**)&wlt,  g_wlt);
    cudaGetSymbolAddress((void**)&wglt, g_wglt);
    cudaGetSymbolAddress((void**)&wgl,  g_wgl);
    cudaGetSymbolAddress((void**)&wql,  g_wql);
    cudaGetSymbolAddress((void**)&u1,   g_u1);
    cudaGetSymbolAddress((void**)&v1,   g_v1);
    cudaGetSymbolAddress((void**)&v0,   g_v0);
    cudaGetSymbolAddress((void**)&zero, g_zero);
    cudaGetSymbolAddress((void**)&kh,   g_kh);
    cudaGetSymbolAddress((void**)&kl,   g_kl);
    cudaGetSymbolAddress((void**)&vh,   g_vh);
    cudaGetSymbolAddress((void**)&vl,   g_vl);

    cudaFuncSetAttribute(gemm_mma<0,0>, cudaFuncAttributeMaxDynamicSharedMemorySize, G2_SMEM_BYTES);
    cudaFuncSetAttribute(gemm_mma<1,1>, cudaFuncAttributeMaxDynamicSharedMemorySize, G2_SMEM_BYTES);
    cudaFuncSetAttribute(attn_mma, cudaFuncAttributeMaxDynamicSharedMemorySize, ATTN2_SMEM);

    dim3 blk(256);

    // ---- prep: weight composition ----
    // WlT (256,768) = Wl^T
    transpose_k<<<dim3(256 / 32, Hdim / 32), dim3(32, 8)>>>(Wl, wlt, Hdim, 256);
    // WglT (256,768) = WlT @ Wg^T   [= (Wg*Wl)^T]
    gemm_mma<0,0><<<dim3(Hdim / 128, 256 / 128), blk, G2_SMEM_BYTES>>>(
        wlt, Wg, zero, zero, wglt, Hdim, Hdim);
    // Wgl (768,256) = WglT^T
    transpose_k<<<dim3(Hdim / 32, 256 / 32), dim3(32, 8)>>>(wglt, wgl, 256, Hdim);
    // Wql (768,256) = Wq @ WglT^T = ipw[0:H] @ Wgl
    gemm_mma<0,0><<<dim3(256 / 128, Hdim / 128), blk, G2_SMEM_BYTES>>>(
        ipw, wglt, zero, zero, wql, Hdim, 256);
    // bias vectors: u1 = Wg@bl ; v1 = Wq@u1 ; v0 = Wq@bg + bq
    matvec_k<<<Hdim / 32, 1024>>>(Wg,  bl, zero, u1, Hdim, Hdim);
    matvec_k<<<Hdim / 32, 1024>>>(ipw, u1, zero, v1, Hdim, Hdim);
    matvec_k<<<Hdim / 32, 1024>>>(ipw, bg, ipb,  v0, Hdim, Hdim);

    dim3 gg(Hdim / 128, Mrows / 128);   // (6, 256)

    // x_time = gcn_mix(x) @ Wgl^T + (bg + m_f*u1)     (K = 256)
    gemm_mma<1,1><<<gg, blk, G2_SMEM_BYTES>>>(x, wgl, bg, u1, x_time, 256, Hdim);
    // q = gcn_mix(x) @ Wql^T + (v0 + m_f*v1)          (K = 256)
    gemm_mma<1,1><<<gg, blk, G2_SMEM_BYTES>>>(x, wql, v0, v1, q, 256, Hdim);
    // k/v projections -> fp16 hi/lo, attention layouts
    kv_kernel2<<<dim3(Hdim / 4, 2), 512>>>(WE, ipw, ipb, kh, kl, vh, vl);
    // fused HMMA attention
    attn_mma<<<dim3(Fdim / 64, NHEAD, Bdim), 512, ATTN2_SMEM>>>(q, kh, kl, vh, vl, o);
    // x_out = o @ out_proj_w^T + out_proj_b           (K = 768)
    gemm_mma<0,0><<<gg, blk, G2_SMEM_BYTES>>>(o, Wo, bo, zero, x_out, Hdim, Hdim);
}

// round 17
// speedup vs baseline: 3.2589x; 1.0648x over previous
#include <cuda_runtime.h>
#include <cuda_fp16.h>
#include <cstdint>
#include <cstddef>

#define Hdim  768
#define Fdim  512
#define Bdim  64
#define Mrows (Bdim * Fdim)       /* 32768 */
#define Vocab 256
#define NHEAD 12
#define DH    64

// ---------------- scratch (no allocations allowed) ----------------
__device__ float  g_q  [(size_t)Mrows * Hdim];
__device__ float  g_o  [(size_t)Mrows * Hdim];
__device__ float  g_wgl [Hdim * 256];      // Wg*Wl (768,256)
__device__ float  g_wql [Hdim * 256];      // Wq*Wg*Wl (768,256)
__device__ float  g_u1 [Hdim];
__device__ float  g_v1 [Hdim];
__device__ float  g_v0 [Hdim];
__device__ float  g_zero[Hdim];            // stays zero (never written)
__device__ __half g_kh[NHEAD * Vocab * DH];   // [head][key][d]
__device__ __half g_kl[NHEAD * Vocab * DH];
__device__ __half g_vh[NHEAD * DH * Vocab];   // [head][d][key]
__device__ __half g_vl[NHEAD * DH * Vocab];

__device__ __forceinline__ uint32_t smem_u32(const void* p) {
    uint32_t r;
    asm("{ .reg .u64 t; cvta.to.shared.u64 t, %1; cvt.u32.u64 %0, t; }"
        : "=r"(r) : "l"(p));
    return r;
}
__device__ __forceinline__ void ldm_x4(uint32_t& r0, uint32_t& r1,
                                       uint32_t& r2, uint32_t& r3, uint32_t addr) {
    asm volatile("ldmatrix.sync.aligned.m8n8.x4.shared.b16 {%0,%1,%2,%3}, [%4];"
                 : "=r"(r0), "=r"(r1), "=r"(r2), "=r"(r3) : "r"(addr));
}
__device__ __forceinline__ void mma16816(float* d, const uint32_t* a,
                                         uint32_t b0, uint32_t b1) {
    asm volatile(
        "mma.sync.aligned.m16n8k16.row.col.f32.f16.f16.f32 "
        "{%0,%1,%2,%3}, {%4,%5,%6,%7}, {%8,%9}, {%0,%1,%2,%3};"
        : "+f"(d[0]), "+f"(d[1]), "+f"(d[2]), "+f"(d[3])
        : "r"(a[0]), "r"(a[1]), "r"(a[2]), "r"(a[3]), "r"(b0), "r"(b1));
}

// ================= HMMA GEMM (double-buffered): C = A*W^T + bias ==========
// BMODE 0: +b0v[col].  BMODE 1: +b0v[col] + m_f*b1v[col], m_f=1.2071 iff (row&511)==1
// TERMS 3: hh + hl + lh.  TERMS 2: hh + hl (drops lo_A*hi_B; ~1e-4 rel err)
#define GSTRIDE 40
#define TILE_H  (128 * GSTRIDE)
#define GBUF_H  (4 * TILE_H)                   /* halves per buffer */
#define G2_SMEM_BYTES (2 * GBUF_H * 2)         /* 81920 B */
#define MF_F1 1.20710678118654752440f

template <int MIX>
__device__ __forceinline__ void stage_load(const float* __restrict__ src,
                                           int row0, int K, int kc, int tid,
                                           float4 st[4])
{
    const int row = tid >> 1;
    const int seg = (tid & 1) << 4;
    const float* p = src + (size_t)(row0 + row) * K + kc + seg;
    st[0] = *(const float4*)(p + 0);
    st[1] = *(const float4*)(p + 4);
    st[2] = *(const float4*)(p + 8);
    st[3] = *(const float4*)(p + 12);
    if (MIX) {
        int f = (row0 + row) & (Fdim - 1);
        if ((unsigned)(f - 1) < 4u) {
            float s1 = (f == 1) ? 0.70710678118654752440f : 0.5f;
#pragma unroll
            for (int j = 0; j < 4; j++) {
                float4 pv = *(const float4*)(p - K + 4 * j);
                st[j].x = 0.5f * st[j].x + s1 * pv.x;
                st[j].y = 0.5f * st[j].y + s1 * pv.y;
                st[j].z = 0.5f * st[j].z + s1 * pv.z;
                st[j].w = 0.5f * st[j].w + s1 * pv.w;
            }
        }
    }
}

__device__ __forceinline__ void stage_store(const float4 st[4], __half* hi,
                                            __half* lo, int tid)
{
    const int row = tid >> 1;
    const int seg = (tid & 1) << 4;
    const float* f = (const float*)st;
    uint32_t hp[8], lp[8];
#pragma unroll
    for (int j = 0; j < 8; j++) {
        float a = f[2 * j], b = f[2 * j + 1];
        __half ha = __float2half_rn(a), hb = __float2half_rn(b);
        float la = a - __half2float(ha), lb = b - __half2float(hb);
        __half2 h2 = __halves2half2(ha, hb);
        __half2 l2 = __floats2half2_rn(la, lb);
        hp[j] = *(uint32_t*)&h2;
        lp[j] = *(uint32_t*)&l2;
    }
    uint32_t off = row * GSTRIDE + seg;
    *(uint4*)(hi + off)     = make_uint4(hp[0], hp[1], hp[2], hp[3]);
    *(uint4*)(hi + off + 8) = make_uint4(hp[4], hp[5], hp[6], hp[7]);
    *(uint4*)(lo + off)     = make_uint4(lp[0], lp[1], lp[2], lp[3]);
    *(uint4*)(lo + off + 8) = make_uint4(lp[4], lp[5], lp[6], lp[7]);
}

template <int MIX, int BMODE, int TERMS>
__global__ void __launch_bounds__(256)
gemm_mma(const float* __restrict__ A, const float* __restrict__ W,
         const float* __restrict__ b0v, const float* __restrict__ b1v,
         float* __restrict__ C, int K, int ldc)
{
    extern __shared__ __align__(16) __half gsm[];
    const int tid = threadIdx.x;
    const int wid = tid >> 5;
    const int ln  = tid & 31;
    const int wm  = wid >> 2;
    const int wn  = wid & 3;
    const int m0  = blockIdx.y << 7;
    const int n0  = blockIdx.x << 7;

    const int lrow  = ln & 15;
    const int lcol8 = (ln >> 4) << 3;
    const uint32_t sb0 = smem_u32(gsm);

    float acc[4][4][4];
#pragma unroll
    for (int i = 0; i < 4; i++)
#pragma unroll
        for (int j = 0; j < 4; j++)
#pragma unroll
            for (int r = 0; r < 4; r++) acc[i][j][r] = 0.f;

    const int nchunk = K >> 5;
    float4 sa[4], sw[4];

    stage_load<MIX>(A, m0, K, 0, tid, sa);
    stage_load<0>  (W, n0, K, 0, tid, sw);
    stage_store(sa, gsm,              gsm + TILE_H,     tid);
    stage_store(sw, gsm + 2 * TILE_H, gsm + 3 * TILE_H, tid);
    __syncthreads();

    for (int c = 0; c < nchunk; c++) {
        if (c + 1 < nchunk) {
            stage_load<MIX>(A, m0, K, (c + 1) << 5, tid, sa);
            stage_load<0>  (W, n0, K, (c + 1) << 5, tid, sw);
        }
        const uint32_t bb = sb0 + (uint32_t)(c & 1) * (GBUF_H * 2);
        const uint32_t uAhi = bb, uAlo = bb + TILE_H * 2;
        const uint32_t uBhi = bb + 2 * TILE_H * 2, uBlo = bb + 3 * TILE_H * 2;
#pragma unroll
        for (int ks = 0; ks < 2; ks++) {
            const uint32_t cadd = (ks * 16 + lcol8) * 2;
            uint32_t ah[4][4], al[4][4], bh[2][4], bl[2][4];
#pragma unroll
            for (int tm = 0; tm < 4; tm++) {
                uint32_t off = ((wm * 64 + tm * 16 + lrow) * GSTRIDE) * 2 + cadd;
                ldm_x4(ah[tm][0], ah[tm][1], ah[tm][2], ah[tm][3], uAhi + off);
                if (TERMS == 3)
                    ldm_x4(al[tm][0], al[tm][1], al[tm][2], al[tm][3], uAlo + off);
            }
#pragma unroll
            for (int pp = 0; pp < 2; pp++) {
                uint32_t off = ((wn * 32 + pp * 16 + lrow) * GSTRIDE) * 2 + cadd;
                ldm_x4(bh[pp][0], bh[pp][1], bh[pp][2], bh[pp][3], uBhi + off);
                ldm_x4(bl[pp][0], bl[pp][1], bl[pp][2], bl[pp][3], uBlo + off);
            }
#pragma unroll
            for (int tm = 0; tm < 4; tm++)
#pragma unroll
                for (int tn = 0; tn < 4; tn++) {
                    const int pp = tn >> 1, ii = tn & 1;
                    uint32_t b0h = bh[pp][ii], b1h = bh[pp][ii + 2];
                    uint32_t b0l = bl[pp][ii], b1l = bl[pp][ii + 2];
                    mma16816(acc[tm][tn], ah[tm], b0h, b1h);
                    mma16816(acc[tm][tn], ah[tm], b0l, b1l);
                    if (TERMS == 3)
                        mma16816(acc[tm][tn], al[tm], b0h, b1h);
                }
        }
        if (c + 1 < nchunk) {
            __half* nb = gsm + (size_t)((c + 1) & 1) * GBUF_H;
            stage_store(sa, nb,              nb + TILE_H,     tid);
            stage_store(sw, nb + 2 * TILE_H, nb + 3 * TILE_H, tid);
        }
        __syncthreads();
    }

    const int g  = ln >> 2;
    const int c2 = (ln & 3) << 1;
#pragma unroll
    for (int tm = 0; tm < 4; tm++) {
#pragma unroll
        for (int tn = 0; tn < 4; tn++) {
            const int col = n0 + wn * 32 + tn * 8 + c2;
            const int r0 = m0 + wm * 64 + tm * 16 + g;
            float bA0, bA1, bB0, bB1;     // biases for row r0 and row r0+8
            if (BMODE == 0) {
                bA0 = bB0 = b0v[col];
                bA1 = bB1 = b0v[col + 1];
            } else {
                const float u0a = b0v[col], u0b = b0v[col + 1];
                const float u1a = b1v[col], u1b = b1v[col + 1];
                const float mf0 = (((r0)     & (Fdim - 1)) == 1) ? MF_F1 : 1.0f;
                const float mf1 = (((r0 + 8) & (Fdim - 1)) == 1) ? MF_F1 : 1.0f;
                bA0 = u0a + mf0 * u1a; bA1 = u0b + mf0 * u1b;
                bB0 = u0a + mf1 * u1a; bB1 = u0b + mf1 * u1b;
            }
            float2 v0 = make_float2(acc[tm][tn][0] + bA0, acc[tm][tn][1] + bA1);
            float2 v1 = make_float2(acc[tm][tn][2] + bB0, acc[tm][tn][3] + bB1);
            *(float2*)(C + (size_t)r0 * ldc + col)       = v0;
            *(float2*)(C + (size_t)(r0 + 8) * ldc + col) = v1;
        }
    }
}

// ---------------- SIMT NN composition GEMM: C(M,N) = A(M,K) @ B(K,N) ------
__global__ void __launch_bounds__(256)
comp_nn(const float* __restrict__ A, const float* __restrict__ B,
        float* __restrict__ C, int M, int N, int K)
{
    __shared__ float As[16][65];
    __shared__ float Bs[16][68];
    const int tid = threadIdx.x;
    const int n0 = blockIdx.x << 6;
    const int m0 = blockIdx.y << 6;
    const int ty = tid >> 4, tx = tid & 15;
    float acc[4][4];
#pragma unroll
    for (int i = 0; i < 4; i++)
#pragma unroll
        for (int j = 0; j < 4; j++) acc[i][j] = 0.f;

    for (int kc = 0; kc < K; kc += 16) {
        {
            int r = tid >> 2, k4 = (tid & 3) << 2;
            float4 v = *(const float4*)(A + (size_t)(m0 + r) * K + kc + k4);
            As[k4 + 0][r] = v.x; As[k4 + 1][r] = v.y;
            As[k4 + 2][r] = v.z; As[k4 + 3][r] = v.w;
        }
        {
            int kr = tid >> 4, n4 = (tid & 15) << 2;
            float4 v = *(const float4*)(B + (size_t)(kc + kr) * N + n0 + n4);
            *(float4*)&Bs[kr][n4] = v;
        }
        __syncthreads();
#pragma unroll
        for (int kk = 0; kk < 16; kk++) {
            float a4[4], b4[4];
#pragma unroll
            for (int i = 0; i < 4; i++) a4[i] = As[kk][ty * 4 + i];
#pragma unroll
            for (int j = 0; j < 4; j++) b4[j] = Bs[kk][tx * 4 + j];
#pragma unroll
            for (int i = 0; i < 4; i++)
#pragma unroll
                for (int j = 0; j < 4; j++) acc[i][j] += a4[i] * b4[j];
        }
        __syncthreads();
    }
#pragma unroll
    for (int i = 0; i < 4; i++)
#pragma unroll
        for (int j = 0; j < 4; j++)
            C[(size_t)(m0 + ty * 4 + i) * N + n0 + tx * 4 + j] = acc[i][j];
}

// ---------------- matvec: y = A(N,K) @ x + c ----------------
__global__ void matvec_k(const float* __restrict__ A, const float* __restrict__ x,
                         const float* __restrict__ c, float* __restrict__ y,
                         int N, int K)
{
    int r  = blockIdx.x * (blockDim.x >> 5) + (threadIdx.x >> 5);
    int ln = threadIdx.x & 31;
    if (r >= N) return;
    float s = 0.f;
    for (int j = ln; j < K; j += 32) s += A[(size_t)r * K + j] * x[j];
#pragma unroll
    for (int o = 16; o; o >>= 1) s += __shfl_xor_sync(0xFFFFFFFFu, s, o);
    if (ln == 0) y[r] = s + c[r];
}

// ---------------- K/V projection: 4 channels/block ------
__global__ void __launch_bounds__(512)
kv_kernel2(const float* __restrict__ WE, const float* __restrict__ ipw,
           const float* __restrict__ ipb,
           __half* __restrict__ kh, __half* __restrict__ kl,
           __half* __restrict__ vh, __half* __restrict__ vl)
{
    __shared__ float part[2][4][Vocab];
    const int nb    = blockIdx.x << 2;
    const int which = blockIdx.y;
    const float* W  = ipw + (size_t)(which + 1) * Hdim * Hdim;
    const int grp   = threadIdx.x >> 8;
    const int vv    = threadIdx.x & 255;
    const int h0    = grp * (Hdim / 2);

    float a[4];
#pragma unroll
    for (int j = 0; j < 4; j++) a[j] = 0.f;
#pragma unroll 4
    for (int h = h0; h < h0 + Hdim / 2; h++) {
        float we = WE[h * Vocab + vv];
#pragma unroll
        for (int j = 0; j < 4; j++)
            a[j] += we * __ldg(W + (size_t)(nb + j) * Hdim + h);
    }
#pragma unroll
    for (int j = 0; j < 4; j++) part[grp][j][vv] = a[j];
    __syncthreads();
    if (grp == 0) {
#pragma unroll
        for (int j = 0; j < 4; j++) {
            int n = nb + j;
            float r = part[0][j][vv] + part[1][j][vv] + ipb[(which + 1) * Hdim + n];
            int head = n >> 6, d = n & 63;
            __half hi = __float2half_rn(r);
            __half lo = __float2half_rn(r - __half2float(hi));
            if (which == 0) {
                size_t o = ((size_t)head * Vocab + vv) * DH + d;   // [head][key][d]
                kh[o] = hi; kl[o] = lo;
            } else {
                size_t o = ((size_t)head * DH + d) * Vocab + vv;   // [head][d][key]
                vh[o] = hi; vl[o] = lo;
            }
        }
    }
}

// ---------------- fused HMMA attention ----------------
#define OFF64(r, c)  ((uint32_t)((r) * 128 + ((((c) >> 3) ^ ((r) & 7)) << 4) + (((c) & 7) << 1)))
#define OFF256(r, c) ((uint32_t)((r) * 512 + ((((c) >> 3) ^ ((r) & 7)) << 4) + (((c) & 7) << 1)))

#define QH_OFF   0
#define QL_OFF   8192
#define KH_OFF   16384
#define KL_OFF   49152
#define VH_OFF   81920
#define VL_OFF   114688
#define PH_OFF   147456
#define PL_OFF   180224
#define RMAX_OFF 212992
#define RSUM_OFF 215040
#define GMAX_OFF 217088
#define RINV_OFF 217344
#define ATTN2_SMEM 217600

__global__ void __launch_bounds__(512)
attn_mma(const float* __restrict__ Q,
         const __half* __restrict__ KHg, const __half* __restrict__ KLg,
         const __half* __restrict__ VHg, const __half* __restrict__ VLg,
         float* __restrict__ O)
{
    extern __shared__ __align__(16) char smc[];
    const uint32_t sb = smem_u32(smc);
    const int tid = threadIdx.x;
    const int wid = tid >> 5;
    const int ln  = tid & 31;
    const int lrow = ln & 15;
    const int lcol8 = (ln >> 4) << 3;
    const int g  = ln >> 2;
    const int c2 = (ln & 3) << 1;
    const int qb = blockIdx.x << 6;
    const int hd = blockIdx.y;
    const int b  = blockIdx.z;

    float* rmax = (float*)(smc + RMAX_OFF);
    float* rsum = (float*)(smc + RSUM_OFF);
    float* gmax = (float*)(smc + GMAX_OFF);
    float* rinv = (float*)(smc + RINV_OFF);

    {
        int m  = tid >> 3;
        int d8 = (tid & 7) << 3;
        const float* p = Q + ((size_t)(b * Fdim + qb + m)) * Hdim + hd * DH + d8;
        float4 v0 = *(const float4*)p;
        float4 v1 = *(const float4*)(p + 4);
        float f8[8] = {v0.x, v0.y, v0.z, v0.w, v1.x, v1.y, v1.z, v1.w};
        uint32_t hp[4], lp[4];
#pragma unroll
        for (int j = 0; j < 4; j++) {
            float a = f8[2 * j], bv = f8[2 * j + 1];
            __half ha = __float2half_rn(a), hb = __float2half_rn(bv);
            float la = a - __half2float(ha), lb = bv - __half2float(hb);
            __half2 h2 = __halves2half2(ha, hb);
            __half2 l2 = __floats2half2_rn(la, lb);
            hp[j] = *(uint32_t*)&h2;
            lp[j] = *(uint32_t*)&l2;
        }
        *(uint4*)(smc + QH_OFF + OFF64(m, d8)) = make_uint4(hp[0], hp[1], hp[2], hp[3]);
        *(uint4*)(smc + QL_OFF + OFF64(m, d8)) = make_uint4(lp[0], lp[1], lp[2], lp[3]);
    }
#pragma unroll
    for (int it = 0; it < 4; it++) {
        int idx = it * 512 + tid;
        int r = idx >> 3, c8 = (idx & 7) << 3;
        size_t go = ((size_t)hd * Vocab + r) * DH + c8;
        *(uint4*)(smc + KH_OFF + OFF64(r, c8)) = *(const uint4*)(KHg + go);
        *(uint4*)(smc + KL_OFF + OFF64(r, c8)) = *(const uint4*)(KLg + go);
        int rv = idx >> 5, cv8 = (idx & 31) << 3;
        size_t gv = ((size_t)hd * DH + rv) * Vocab + cv8;
        *(uint4*)(smc + VH_OFF + OFF256(rv, cv8)) = *(const uint4*)(VHg + gv);
        *(uint4*)(smc + VL_OFF + OFF256(rv, cv8)) = *(const uint4*)(VLg + gv);
    }
    __syncthreads();

    float acc[2][4][4];
#pragma unroll
    for (int i = 0; i < 2; i++)
#pragma unroll
        for (int j = 0; j < 4; j++)
#pragma unroll
            for (int r = 0; r < 4; r++) acc[i][j][r] = 0.f;
    {
        const int wm = wid >> 3, wn = wid & 7;
#pragma unroll
        for (int ks = 0; ks < 4; ks++) {
            const int kb = ks * 16 + lcol8;
            uint32_t ah[2][4], al[2][4], bh[2][4], bl[2][4];
#pragma unroll
            for (int tm = 0; tm < 2; tm++) {
                int r = wm * 32 + tm * 16 + lrow;
                ldm_x4(ah[tm][0], ah[tm][1], ah[tm][2], ah[tm][3], sb + QH_OFF + OFF64(r, kb));
                ldm_x4(al[tm][0], al[tm][1], al[tm][2], al[tm][3], sb + QL_OFF + OFF64(r, kb));
            }
#pragma unroll
            for (int pp = 0; pp < 2; pp++) {
                int r = wn * 32 + pp * 16 + lrow;
                ldm_x4(bh[pp][0], bh[pp][1], bh[pp][2], bh[pp][3], sb + KH_OFF + OFF64(r, kb));
                ldm_x4(bl[pp][0], bl[pp][1], bl[pp][2], bl[pp][3], sb + KL_OFF + OFF64(r, kb));
            }
#pragma unroll
            for (int tm = 0; tm < 2; tm++)
#pragma unroll
                for (int tn = 0; tn < 4; tn++) {
                    const int pp = tn >> 1, ii = tn & 1;
                    mma16816(acc[tm][tn], ah[tm], bh[pp][ii], bh[pp][ii + 2]);
                    mma16816(acc[tm][tn], ah[tm], bl[pp][ii], bl[pp][ii + 2]);
                    mma16816(acc[tm][tn], al[tm], bh[pp][ii], bh[pp][ii + 2]);
                }
        }
#pragma unroll
        for (int i = 0; i < 2; i++)
#pragma unroll
            for (int j = 0; j < 4; j++)
#pragma unroll
                for (int r = 0; r < 4; r++) acc[i][j][r] *= 0.125f;

#pragma unroll
        for (int tm = 0; tm < 2; tm++) {
            float m0 = -1e30f, m1 = -1e30f;
#pragma unroll
            for (int tn = 0; tn < 4; tn++) {
                m0 = fmaxf(m0, fmaxf(acc[tm][tn][0], acc[tm][tn][1]));
                m1 = fmaxf(m1, fmaxf(acc[tm][tn][2], acc[tm][tn][3]));
            }
            m0 = fmaxf(m0, __shfl_xor_sync(0xFFFFFFFFu, m0, 1));
            m0 = fmaxf(m0, __shfl_xor_sync(0xFFFFFFFFu, m0, 2));
            m1 = fmaxf(m1, __shfl_xor_sync(0xFFFFFFFFu, m1, 1));
            m1 = fmaxf(m1, __shfl_xor_sync(0xFFFFFFFFu, m1, 2));
            if ((ln & 3) == 0) {
                int r0 = wm * 32 + tm * 16 + g;
                rmax[wn * 64 + r0]     = m0;
                rmax[wn * 64 + r0 + 8] = m1;
            }
        }
        __syncthreads();
        if (tid < 64) {
            float mm = rmax[tid];
#pragma unroll
            for (int w = 1; w < 8; w++) mm = fmaxf(mm, rmax[w * 64 + tid]);
            gmax[tid] = mm;
        }
        __syncthreads();
#pragma unroll
        for (int tm = 0; tm < 2; tm++) {
            const int r0 = wm * 32 + tm * 16 + g, r1 = r0 + 8;
            const float gm0 = gmax[r0], gm1 = gmax[r1];
            float s0 = 0.f, s1 = 0.f;
#pragma unroll
            for (int tn = 0; tn < 4; tn++) {
                const int col = wn * 32 + tn * 8 + c2;
                float e0 = __expf(acc[tm][tn][0] - gm0);
                float e1 = __expf(acc[tm][tn][1] - gm0);
                float e2 = __expf(acc[tm][tn][2] - gm1);
                float e3 = __expf(acc[tm][tn][3] - gm1);
                s0 += e0 + e1; s1 += e2 + e3;
                __half h0 = __float2half_rn(e0), h1 = __float2half_rn(e1);
                __half h2 = __float2half_rn(e2), h3 = __float2half_rn(e3);
                __half2 hp0 = __halves2half2(h0, h1), hp1 = __halves2half2(h2, h3);
                __half2 lp0 = __floats2half2_rn(e0 - __half2float(h0), e1 - __half2float(h1));
                __half2 lp1 = __floats2half2_rn(e2 - __half2float(h2), e3 - __half2float(h3));
                *(uint32_t*)(smc + PH_OFF + OFF256(r0, col)) = *(uint32_t*)&hp0;
                *(uint32_t*)(smc + PH_OFF + OFF256(r1, col)) = *(uint32_t*)&hp1;
                *(uint32_t*)(smc + PL_OFF + OFF256(r0, col)) = *(uint32_t*)&lp0;
                *(uint32_t*)(smc + PL_OFF + OFF256(r1, col)) = *(uint32_t*)&lp1;
            }
            s0 += __shfl_xor_sync(0xFFFFFFFFu, s0, 1);
            s0 += __shfl_xor_sync(0xFFFFFFFFu, s0, 2);
            s1 += __shfl_xor_sync(0xFFFFFFFFu, s1, 1);
            s1 += __shfl_xor_sync(0xFFFFFFFFu, s1, 2);
            if ((ln & 3) == 0) {
                rsum[wn * 64 + r0] = s0;
                rsum[wn * 64 + r1] = s1;
            }
        }
        __syncthreads();
        if (tid < 64) {
            float s = 0.f;
#pragma unroll
            for (int w = 0; w < 8; w++) s += rsum[w * 64 + tid];
            rinv[tid] = 1.0f / s;
        }
        __syncthreads();
    }

    {
        const int wm2 = wid >> 2, wn2 = wid & 3;
        float a2[2][4];
#pragma unroll
        for (int j = 0; j < 2; j++)
#pragma unroll
            for (int r = 0; r < 4; r++) a2[j][r] = 0.f;
#pragma unroll 4
        for (int ks = 0; ks < 16; ks++) {
            const int kb = ks * 16 + lcol8;
            uint32_t pa[4], pl4[4], vb[4], vl4[4];
            const int ra = wm2 * 16 + lrow;
            ldm_x4(pa[0], pa[1], pa[2], pa[3],   sb + PH_OFF + OFF256(ra, kb));
            ldm_x4(pl4[0], pl4[1], pl4[2], pl4[3], sb + PL_OFF + OFF256(ra, kb));
            const int rb = wn2 * 16 + lrow;
            ldm_x4(vb[0], vb[1], vb[2], vb[3],   sb + VH_OFF + OFF256(rb, kb));
            ldm_x4(vl4[0], vl4[1], vl4[2], vl4[3], sb + VL_OFF + OFF256(rb, kb));
#pragma unroll
            for (int tn = 0; tn < 2; tn++) {
                mma16816(a2[tn], pa,  vb[tn],  vb[tn + 2]);
                mma16816(a2[tn], pa,  vl4[tn], vl4[tn + 2]);
                mma16816(a2[tn], pl4, vb[tn],  vb[tn + 2]);
            }
        }
#pragma unroll
        for (int tn = 0; tn < 2; tn++) {
            const int col = hd * DH + wn2 * 16 + tn * 8 + c2;
            const int r0 = wm2 * 16 + g;
            const float iv0 = rinv[r0], iv1 = rinv[r0 + 8];
            float2 v0 = make_float2(a2[tn][0] * iv0, a2[tn][1] * iv0);
            float2 v1 = make_float2(a2[tn][2] * iv1, a2[tn][3] * iv1);
            *(float2*)(O + ((size_t)(b * Fdim + qb + r0)) * Hdim + col)     = v0;
            *(float2*)(O + ((size_t)(b * Fdim + qb + r0 + 8)) * Hdim + col) = v1;
        }
    }
}

// ---------------- launch ----------------
extern "C" void kernel_launch(void* const* d_in, const int* in_sizes, int n_in,
                              void* d_out, int out_size)
{
    const float* x   = (const float*)d_in[0];
    const float* WE  = (const float*)d_in[1];
    const float* Wl  = (const float*)d_in[2];
    const float* bl  = (const float*)d_in[3];
    const float* Wg  = (const float*)d_in[4];
    const float* bg  = (const float*)d_in[5];
    const float* ipw = (const float*)d_in[6];
    const float* ipb = (const float*)d_in[7];
    const float* Wo  = (const float*)d_in[8];
    const float* bo  = (const float*)d_in[9];

    float* out    = (float*)d_out;
    float* x_time = out;
    float* x_out  = out + (size_t)Mrows * Hdim;

    float *q, *o, *wgl, *wql, *u1, *v1, *v0, *zero;
    __half *kh, *kl, *vh, *vl;
    cudaGetSymbolAddress((void**)&q,    g_q);
    cudaGetSymbolAddress((void**)&o,    g_o);
    cudaGetSymbolAddress((void**)&wgl,  g_wgl);
    cudaGetSymbolAddress((void**)&wql,  g_wql);
    cudaGetSymbolAddress((void**)&u1,   g_u1);
    cudaGetSymbolAddress((void**)&v1,   g_v1);
    cudaGetSymbolAddress((void**)&v0,   g_v0);
    cudaGetSymbolAddress((void**)&zero, g_zero);
    cudaGetSymbolAddress((void**)&kh,   g_kh);
    cudaGetSymbolAddress((void**)&kl,   g_kl);
    cudaGetSymbolAddress((void**)&vh,   g_vh);
    cudaGetSymbolAddress((void**)&vl,   g_vl);

    cudaFuncSetAttribute(gemm_mma<1,1,3>, cudaFuncAttributeMaxDynamicSharedMemorySize, G2_SMEM_BYTES);
    cudaFuncSetAttribute(gemm_mma<0,0,2>, cudaFuncAttributeMaxDynamicSharedMemorySize, G2_SMEM_BYTES);
    cudaFuncSetAttribute(attn_mma, cudaFuncAttributeMaxDynamicSharedMemorySize, ATTN2_SMEM);

    dim3 blk(256);

    // ---- prep: weight composition (SIMT NN gemms, no transposes) ----
    // Wgl (768,256) = Wg @ Wl
    comp_nn<<<dim3(256 / 64, Hdim / 64), blk>>>(Wg, Wl, wgl, Hdim, 256, Hdim);
    // Wql (768,256) = Wq @ Wgl
    comp_nn<<<dim3(256 / 64, Hdim / 64), blk>>>(ipw, wgl, wql, Hdim, 256, Hdim);
    // bias vectors: u1 = Wg@bl ; v1 = Wq@u1 ; v0 = Wq@bg + bq
    matvec_k<<<Hdim / 32, 1024>>>(Wg,  bl, zero, u1, Hdim, Hdim);
    matvec_k<<<Hdim / 32, 1024>>>(ipw, u1, zero, v1, Hdim, Hdim);
    matvec_k<<<Hdim / 32, 1024>>>(ipw, bg, ipb,  v0, Hdim, Hdim);

    dim3 gg(Hdim / 128, Mrows / 128);   // (6, 256)

    // x_time = gcn_mix(x) @ Wgl^T + (bg + m_f*u1)     (K = 256)
    gemm_mma<1,1,3><<<gg, blk, G2_SMEM_BYTES>>>(x, wgl, bg, u1, x_time, 256, Hdim);
    // q = gcn_mix(x) @ Wql^T + (v0 + m_f*v1)          (K = 256)
    gemm_mma<1,1,3><<<gg, blk, G2_SMEM_BYTES>>>(x, wql, v0, v1, q, 256, Hdim);
    // k/v projections -> fp16 hi/lo, attention layouts
    kv_kernel2<<<dim3(Hdim / 4, 2), 512>>>(WE, ipw, ipb, kh, kl, vh, vl);
    // fused HMMA attention
    attn_mma<<<dim3(Fdim / 64, NHEAD, Bdim), 512, ATTN2_SMEM>>>(q, kh, kl, vh, vl, o);
    // x_out = o @ out_proj_w^T + out_proj_b           (K = 768, 2-term split)
    gemm_mma<0,0,2><<<gg, blk, G2_SMEM_BYTES>>>(o, Wo, bo, zero, x_out, Hdim, Hdim);
}